// round 1
// baseline (speedup 1.0000x reference)
#include <cuda_runtime.h>
#include <cuda_bf16.h>

// ---------------- problem constants ----------------
#define B_TOK   1024
#define NA      32
#define DZ      96
#define DA      32
#define DMODEL  128
#define ND      4096      // NA*DMODEL
#define NEXP    8
#define FF      1024
#define HH      512
#define NR      4
#define NHEADS  4
#define HDIM    32
#define KTOP    2

// ---------------- scratch (no cudaMalloc allowed) ----------------
__device__ float g_x[B_TOK * ND];        // concat(z,a)      16.8 MB
__device__ float g_y[B_TOK * ND];        // MoE output       16.8 MB
__device__ float g_hid[B_TOK * HH];      // head hidden       2 MB
__device__ float g_lse[B_TOK];           // per-token logsumexp
__device__ int   g_topidx[B_TOK * KTOP];
__device__ float g_topgate[B_TOK * KTOP];

// ---------------- kernel 1: concat ----------------
__global__ void k_concat(const float* __restrict__ z, const float* __restrict__ a) {
    int idx = blockIdx.x * 256 + threadIdx.x;          // 0 .. B*ND-1
    int dd = idx & 127;
    int row = idx >> 7;                                 // b*NA + n
    g_x[idx] = (dd < DZ) ? z[row * DZ + dd] : a[row * DA + (dd - DZ)];
}

// ---------------- kernel 2: router ----------------
__global__ __launch_bounds__(256) void k_router(const float* __restrict__ w_gate,
                                                float* __restrict__ gates_out) {
    __shared__ float red[256 * 8];
    int b = blockIdx.x, tid = threadIdx.x;
    float p[8];
#pragma unroll
    for (int e = 0; e < 8; e++) p[e] = 0.f;
    const float* xb = g_x + b * ND;
    for (int k = tid; k < ND; k += 256) {
        float xv = xb[k];
        const float4* wg = reinterpret_cast<const float4*>(w_gate + k * 8);
        float4 w0 = wg[0], w1 = wg[1];
        p[0] = fmaf(xv, w0.x, p[0]); p[1] = fmaf(xv, w0.y, p[1]);
        p[2] = fmaf(xv, w0.z, p[2]); p[3] = fmaf(xv, w0.w, p[3]);
        p[4] = fmaf(xv, w1.x, p[4]); p[5] = fmaf(xv, w1.y, p[5]);
        p[6] = fmaf(xv, w1.z, p[6]); p[7] = fmaf(xv, w1.w, p[7]);
    }
#pragma unroll
    for (int e = 0; e < 8; e++) red[tid * 8 + e] = p[e];
    __syncthreads();
    for (int s = 128; s > 0; s >>= 1) {
        if (tid < s) {
#pragma unroll
            for (int e = 0; e < 8; e++) red[tid * 8 + e] += red[(tid + s) * 8 + e];
        }
        __syncthreads();
    }
    if (tid == 0) {
        float l[8];
#pragma unroll
        for (int e = 0; e < 8; e++) l[e] = red[e];
        // top-1
        int i0 = 0; float v0 = l[0];
#pragma unroll
        for (int e = 1; e < 8; e++) if (l[e] > v0) { v0 = l[e]; i0 = e; }
        // top-2
        int i1 = -1; float v1 = -3.4e38f;
#pragma unroll
        for (int e = 0; e < 8; e++) if (e != i0 && l[e] > v1) { v1 = l[e]; i1 = e; }
        float e1 = expf(v1 - v0);
        float inv = 1.f / (1.f + e1);
        float g0 = inv, g1v = e1 * inv;
#pragma unroll
        for (int e = 0; e < 8; e++)
            gates_out[b * 8 + e] = (e == i0) ? g0 : ((e == i1) ? g1v : 0.f);
        g_topidx[b * 2] = i0;  g_topidx[b * 2 + 1] = i1;
        g_topgate[b * 2] = g0; g_topgate[b * 2 + 1] = g1v;
        float s = 0.f;
#pragma unroll
        for (int e = 0; e < 8; e++) s += expf(l[e] - v0);
        g_lse[b] = v0 + logf(s);
    }
}

// ---------------- kernel 3: expert (one block per token) ----------------
// dynamic smem layout (floats): s_x[32*128] | s_qkv[32*384] | s_h[32*128] | s_t[32*256]
#define EXPERT_SMEM_FLOATS (4096 + 12288 + 4096 + 8192)
#define EXPERT_SMEM_BYTES  (EXPERT_SMEM_FLOATS * 4)

__global__ __launch_bounds__(256, 2) void k_expert(
    const float* __restrict__ w_in,  const float* __restrict__ b_in,
    const float* __restrict__ w_out, const float* __restrict__ b_out,
    const float* __restrict__ ln1_g, const float* __restrict__ ln1_b,
    const float* __restrict__ fw1,   const float* __restrict__ fb1,
    const float* __restrict__ fw2,   const float* __restrict__ fb2,
    const float* __restrict__ ln2_g, const float* __restrict__ ln2_b) {
    extern __shared__ float smem[];
    float* s_x   = smem;                  // [32][128]
    float* s_qkv = smem + 4096;           // [32][384]
    float* s_h   = smem + 4096 + 12288;   // [32][128]
    float* s_t   = smem + 4096 + 12288 + 4096; // [32][256]

    int b   = blockIdx.x;
    int tid = threadIdx.x;
    int lane = tid & 31, warp = tid >> 5;
    int d_col = tid & 127;
    int rh = tid >> 7;                    // 0/1 row-half

    // load x tile
    {
        const float4* xg = reinterpret_cast<const float4*>(g_x + b * ND);
        float4* sx4 = reinterpret_cast<float4*>(s_x);
        for (int i = tid; i < 1024; i += 256) sx4[i] = xg[i];
    }
    __syncthreads();

    for (int slot = 0; slot < 2; slot++) {
        int e = g_topidx[b * 2 + slot];
        float gate = g_topgate[b * 2 + slot];
        const float* wi  = w_in  + e * (384 * 128);
        const float* bi  = b_in  + e * 384;
        const float* wo  = w_out + e * (128 * 128);
        const float* bo  = b_out + e * 128;
        const float* g1  = ln1_g + e * 128;
        const float* be1 = ln1_b + e * 128;
        const float* W1  = fw1 + e * (1024 * 128);
        const float* Bb1 = fb1 + e * 1024;
        const float* W2  = fw2 + e * (128 * 1024);
        const float* Bb2 = fb2 + e * 128;
        const float* g2  = ln2_g + e * 128;
        const float* be2 = ln2_b + e * 128;

        // ---- qkv = x @ wi^T + bi : cols 384, K=128 ----
        for (int col = tid; col < 384; col += 256) {
            float acc[32];
            float bv = bi[col];
#pragma unroll
            for (int i = 0; i < 32; i++) acc[i] = bv;
            const float4* w = reinterpret_cast<const float4*>(wi + col * 128);
            for (int k4 = 0; k4 < 32; k4++) {
                float4 w4 = w[k4];
#pragma unroll
                for (int i = 0; i < 32; i++) {
                    float4 x4 = *reinterpret_cast<const float4*>(s_x + i * 128 + k4 * 4);
                    acc[i] = fmaf(x4.x, w4.x, fmaf(x4.y, w4.y, fmaf(x4.z, w4.z, fmaf(x4.w, w4.w, acc[i]))));
                }
            }
#pragma unroll
            for (int i = 0; i < 32; i++) s_qkv[i * 384 + col] = acc[i];
        }
        __syncthreads();

        // ---- attention: warp pair per head, lane = key (then lane = dim) ----
        {
            int h = warp >> 1;
            int q0 = (warp & 1) * 16;
            float kreg[32];
            const float4* kp = reinterpret_cast<const float4*>(s_qkv + lane * 384 + 128 + h * 32);
#pragma unroll
            for (int d4 = 0; d4 < 8; d4++) {
                float4 k4 = kp[d4];
                kreg[d4 * 4 + 0] = k4.x; kreg[d4 * 4 + 1] = k4.y;
                kreg[d4 * 4 + 2] = k4.z; kreg[d4 * 4 + 3] = k4.w;
            }
            for (int q = q0; q < q0 + 16; q++) {
                const float4* qp = reinterpret_cast<const float4*>(s_qkv + q * 384 + h * 32);
                float sc = 0.f;
#pragma unroll
                for (int d4 = 0; d4 < 8; d4++) {
                    float4 q4 = qp[d4];
                    sc += q4.x * kreg[d4 * 4] + q4.y * kreg[d4 * 4 + 1]
                        + q4.z * kreg[d4 * 4 + 2] + q4.w * kreg[d4 * 4 + 3];
                }
                sc *= 0.1767766952966369f;   // 1/sqrt(32)
                float m = sc;
#pragma unroll
                for (int off = 16; off > 0; off >>= 1)
                    m = fmaxf(m, __shfl_xor_sync(0xffffffffu, m, off));
                float p = expf(sc - m);
                float ssum = p;
#pragma unroll
                for (int off = 16; off > 0; off >>= 1)
                    ssum += __shfl_xor_sync(0xffffffffu, ssum, off);
                float att = p / ssum;
                float o = 0.f;
#pragma unroll
                for (int kk = 0; kk < 32; kk++) {
                    float av = __shfl_sync(0xffffffffu, att, kk);
                    o = fmaf(av, s_qkv[kk * 384 + 256 + h * 32 + lane], o);
                }
                s_t[q * 128 + h * 32 + lane] = o;
            }
        }
        __syncthreads();

        // ---- o-proj + residual -> s_h ----
        {
            float acc[16];
            float bv = bo[d_col];
#pragma unroll
            for (int i = 0; i < 16; i++) acc[i] = bv;
            const float4* w = reinterpret_cast<const float4*>(wo + d_col * 128);
            for (int k4 = 0; k4 < 32; k4++) {
                float4 w4 = w[k4];
#pragma unroll
                for (int i = 0; i < 16; i++) {
                    int row = rh * 16 + i;
                    float4 o4 = *reinterpret_cast<const float4*>(s_t + row * 128 + k4 * 4);
                    acc[i] = fmaf(o4.x, w4.x, fmaf(o4.y, w4.y, fmaf(o4.z, w4.z, fmaf(o4.w, w4.w, acc[i]))));
                }
            }
#pragma unroll
            for (int i = 0; i < 16; i++) {
                int row = rh * 16 + i;
                s_h[row * 128 + d_col] = s_x[row * 128 + d_col] + acc[i];
            }
        }
        __syncthreads();

        // ---- LN1 in place on s_h: warp per 4 rows ----
        {
#pragma unroll
            for (int rr = 0; rr < 4; rr++) {
                int r = warp * 4 + rr;
                float v[4]; float sum = 0.f, sq = 0.f;
#pragma unroll
                for (int j = 0; j < 4; j++) {
                    v[j] = s_h[r * 128 + lane + 32 * j];
                    sum += v[j]; sq += v[j] * v[j];
                }
#pragma unroll
                for (int off = 16; off > 0; off >>= 1) {
                    sum += __shfl_xor_sync(0xffffffffu, sum, off);
                    sq  += __shfl_xor_sync(0xffffffffu, sq, off);
                }
                float mu = sum * (1.f / 128.f);
                float var = sq * (1.f / 128.f) - mu * mu;
                float rs = rsqrtf(var + 1e-5f);
#pragma unroll
                for (int j = 0; j < 4; j++) {
                    int dd = lane + 32 * j;
                    s_h[r * 128 + dd] = (v[j] - mu) * rs * g1[dd] + be1[dd];
                }
            }
        }
        __syncthreads();

        // ---- FFN: 4 chunks of 256 hidden, fused relu + second GEMM ----
        float facc[16];
        {
            float bv = Bb2[d_col];
#pragma unroll
            for (int i = 0; i < 16; i++) facc[i] = bv;
        }
        for (int c = 0; c < 4; c++) {
            int j = c * 256 + tid;
            float acc[32];
            float bv = Bb1[j];
#pragma unroll
            for (int i = 0; i < 32; i++) acc[i] = bv;
            const float4* w = reinterpret_cast<const float4*>(W1 + j * 128);
            for (int k4 = 0; k4 < 32; k4++) {
                float4 w4 = w[k4];
#pragma unroll
                for (int i = 0; i < 32; i++) {
                    float4 h4 = *reinterpret_cast<const float4*>(s_h + i * 128 + k4 * 4);
                    acc[i] = fmaf(h4.x, w4.x, fmaf(h4.y, w4.y, fmaf(h4.z, w4.z, fmaf(h4.w, w4.w, acc[i]))));
                }
            }
            __syncthreads();   // prior chunk's s_t readers done
#pragma unroll
            for (int i = 0; i < 32; i++) s_t[i * 256 + tid] = fmaxf(acc[i], 0.f);
            __syncthreads();
            const float4* w2p = reinterpret_cast<const float4*>(W2 + d_col * 1024 + c * 256);
            for (int k4 = 0; k4 < 64; k4++) {
                float4 w4 = w2p[k4];
#pragma unroll
                for (int i = 0; i < 16; i++) {
                    int row = rh * 16 + i;
                    float4 t4 = *reinterpret_cast<const float4*>(s_t + row * 256 + k4 * 4);
                    facc[i] = fmaf(t4.x, w4.x, fmaf(t4.y, w4.y, fmaf(t4.z, w4.z, fmaf(t4.w, w4.w, facc[i]))));
                }
            }
        }
        __syncthreads();
        // residual (h + f) -> s_t (stride 128)
#pragma unroll
        for (int i = 0; i < 16; i++) {
            int row = rh * 16 + i;
            s_t[row * 128 + d_col] = s_h[row * 128 + d_col] + facc[i];
        }
        __syncthreads();

        // ---- LN2 + gate-weighted accumulation into g_y ----
        {
            float* yb = g_y + b * ND;
#pragma unroll
            for (int rr = 0; rr < 4; rr++) {
                int r = warp * 4 + rr;
                float v[4]; float sum = 0.f, sq = 0.f;
#pragma unroll
                for (int j = 0; j < 4; j++) {
                    v[j] = s_t[r * 128 + lane + 32 * j];
                    sum += v[j]; sq += v[j] * v[j];
                }
#pragma unroll
                for (int off = 16; off > 0; off >>= 1) {
                    sum += __shfl_xor_sync(0xffffffffu, sum, off);
                    sq  += __shfl_xor_sync(0xffffffffu, sq, off);
                }
                float mu = sum * (1.f / 128.f);
                float var = sq * (1.f / 128.f) - mu * mu;
                float rs = rsqrtf(var + 1e-5f);
#pragma unroll
                for (int j = 0; j < 4; j++) {
                    int dd = lane + 32 * j;
                    float val = (v[j] - mu) * rs * g2[dd] + be2[dd];
                    float contrib = gate * val;
                    if (slot == 0) yb[r * 128 + dd] = contrib;
                    else           yb[r * 128 + dd] += contrib;
                }
            }
        }
        __syncthreads();   // smem reuse safety before next slot
    }
}

// ---------------- kernel 4: head GEMM1  hid = relu(y @ hw1^T + hb1) ----------------
__global__ __launch_bounds__(256) void k_head1(const float* __restrict__ hw1,
                                               const float* __restrict__ hb1) {
    __shared__ float sA[32][65];
    __shared__ float sB[32][65];
    int bm = blockIdx.x * 64, bn = blockIdx.y * 64;
    int tx = threadIdx.x & 15, ty = threadIdx.x >> 4;
    float acc[4][4];
#pragma unroll
    for (int i = 0; i < 4; i++)
#pragma unroll
        for (int j = 0; j < 4; j++) acc[i][j] = 0.f;

    for (int k0 = 0; k0 < ND; k0 += 32) {
        for (int i = threadIdx.x; i < 2048; i += 256) {
            int m = i >> 5, k = i & 31;
            sA[k][m] = g_y[(bm + m) * ND + k0 + k];
            sB[k][m] = hw1[(bn + m) * ND + k0 + k];
        }
        __syncthreads();
#pragma unroll
        for (int k = 0; k < 32; k++) {
            float a[4], bb[4];
#pragma unroll
            for (int i = 0; i < 4; i++) { a[i] = sA[k][ty * 4 + i]; bb[i] = sB[k][tx * 4 + i]; }
#pragma unroll
            for (int i = 0; i < 4; i++)
#pragma unroll
                for (int j = 0; j < 4; j++) acc[i][j] = fmaf(a[i], bb[j], acc[i][j]);
        }
        __syncthreads();
    }
#pragma unroll
    for (int i = 0; i < 4; i++) {
        int m = bm + ty * 4 + i;
#pragma unroll
        for (int j = 0; j < 4; j++) {
            int n = bn + tx * 4 + j;
            g_hid[m * HH + n] = fmaxf(acc[i][j] + hb1[n], 0.f);
        }
    }
}

// ---------------- kernel 5: head GEMV2  r = hid @ hw2^T + hb2 ----------------
__global__ void k_head2(const float* __restrict__ hw2, const float* __restrict__ hb2,
                        float* __restrict__ out_r) {
    int b = blockIdx.x;
    int j = threadIdx.x >> 5;       // warp -> output (4 warps)
    int lane = threadIdx.x & 31;
    const float* hb = g_hid + b * HH;
    const float* w = hw2 + j * HH;
    float s = 0.f;
    for (int k = lane; k < HH; k += 32) s = fmaf(hb[k], w[k], s);
#pragma unroll
    for (int off = 16; off > 0; off >>= 1) s += __shfl_xor_sync(0xffffffffu, s, off);
    if (lane == 0) out_r[b * NR + j] = s + hb2[j];
}

// ---------------- kernel 6: loss_bal ----------------
__global__ void k_loss(const float* __restrict__ gates, float* __restrict__ out_loss) {
    __shared__ float s_imp[8][32], s_ld[8][32], s_lse[256];
    int t = threadIdx.x;
    int e = t & 7, c = t >> 3;
    float imp = 0.f, ld = 0.f;
    for (int b = c; b < B_TOK; b += 32) {
        float g = gates[b * 8 + e];
        imp += g;
        if (g > 0.f) ld += 1.f;
    }
    s_imp[e][c] = imp; s_ld[e][c] = ld;
    float ls = 0.f;
    for (int b = t; b < B_TOK; b += 256) ls += g_lse[b];
    s_lse[t] = ls;
    __syncthreads();
    for (int s = 128; s > 0; s >>= 1) {
        if (t < s) s_lse[t] += s_lse[t + s];
        __syncthreads();
    }
    if (t == 0) {
        float I[8], L[8];
        float mi = 0.f, ml = 0.f;
        for (int e2 = 0; e2 < 8; e2++) {
            float si = 0.f, sl = 0.f;
            for (int c2 = 0; c2 < 32; c2++) { si += s_imp[e2][c2]; sl += s_ld[e2][c2]; }
            I[e2] = si; L[e2] = sl; mi += si; ml += sl;
        }
        mi *= 0.125f; ml *= 0.125f;
        float vi = 0.f, vl = 0.f;
        for (int e2 = 0; e2 < 8; e2++) {
            vi += (I[e2] - mi) * (I[e2] - mi);
            vl += (L[e2] - ml) * (L[e2] - ml);
        }
        vi /= 7.f; vl /= 7.f;
        float loss = vi / (mi * mi + 1e-10f) + vl / (ml * ml + 1e-10f)
                   + s_lse[0] * (1.f / (float)B_TOK);
        *out_loss = loss;
    }
}

// ---------------- launch ----------------
extern "C" void kernel_launch(void* const* d_in, const int* in_sizes, int n_in,
                              void* d_out, int out_size) {
    const float* z      = (const float*)d_in[0];
    const float* a      = (const float*)d_in[1];
    const float* w_gate = (const float*)d_in[2];
    const float* w_in   = (const float*)d_in[3];
    const float* b_in   = (const float*)d_in[4];
    const float* w_out  = (const float*)d_in[5];
    const float* b_out  = (const float*)d_in[6];
    const float* ln1_g  = (const float*)d_in[7];
    const float* ln1_b  = (const float*)d_in[8];
    const float* w1     = (const float*)d_in[9];
    const float* b1     = (const float*)d_in[10];
    const float* w2     = (const float*)d_in[11];
    const float* b2     = (const float*)d_in[12];
    const float* ln2_g  = (const float*)d_in[13];
    const float* ln2_b  = (const float*)d_in[14];
    const float* hw1    = (const float*)d_in[15];
    const float* hb1    = (const float*)d_in[16];
    const float* hw2    = (const float*)d_in[17];
    const float* hb2    = (const float*)d_in[18];

    float* out       = (float*)d_out;
    float* gates_out = out + B_TOK * NR;                  // [1024, 8]
    float* loss_out  = out + B_TOK * NR + B_TOK * NEXP;   // scalar

    cudaFuncSetAttribute(k_expert, cudaFuncAttributeMaxDynamicSharedMemorySize,
                         EXPERT_SMEM_BYTES);

    k_concat<<<(B_TOK * ND) / 256, 256>>>(z, a);
    k_router<<<B_TOK, 256>>>(w_gate, gates_out);
    k_expert<<<B_TOK, 256, EXPERT_SMEM_BYTES>>>(w_in, b_in, w_out, b_out,
                                                ln1_g, ln1_b, w1, b1, w2, b2,
                                                ln2_g, ln2_b);
    k_head1<<<dim3(B_TOK / 64, HH / 64), 256>>>(hw1, hb1);
    k_head2<<<B_TOK, 128>>>(hw2, hb2, out);
    k_loss<<<1, 256>>>(gates_out, loss_out);
}

// round 3
// speedup vs baseline: 2.4354x; 2.4354x over previous
#include <cuda_runtime.h>
#include <cuda_bf16.h>
#include <cstdint>

// ---------------- problem constants ----------------
#define B_TOK   1024
#define NA      32
#define DZ      96
#define DA      32
#define DMODEL  128
#define ND      4096      // NA*DMODEL
#define NEXP    8
#define FF      1024
#define HH      512
#define NR      4
#define KTOP    2

#define PAIR_MAX  2072    // 2048 pairs + worst-case padding (8 experts * 3)
#define GROUP_MAX 518     // PAIR_MAX / 4

// ---------------- scratch (__device__ globals; no cudaMalloc allowed) ----------------
__device__ float g_x[B_TOK * ND];                    // concat(z,a)        16.8 MB
__device__ float g_y[B_TOK * ND];                    // MoE output         16.8 MB
__device__ float g_qkv[(size_t)PAIR_MAX * 32 * 384]; //                   101.8 MB
__device__ float g_ao [(size_t)PAIR_MAX * 32 * 128]; // attn out           33.9 MB
__device__ float g_o  [(size_t)PAIR_MAX * 32 * 128]; // o-proj out         33.9 MB
__device__ float g_h  [(size_t)PAIR_MAX * 32 * 128]; // post-LN1           33.9 MB
__device__ float g_f2 [(size_t)PAIR_MAX * 32 * 128]; // FFN out            33.9 MB
__device__ float g_hid[B_TOK * HH];
__device__ float g_lse[B_TOK];
__device__ int   g_topidx[B_TOK * KTOP];
__device__ float g_topgate[B_TOK * KTOP];

__device__ int   g_ngroups;
__device__ int   g_npad;
__device__ int   g_grp_expert[GROUP_MAX];
__device__ int   g_sp_pair[PAIR_MAX];    // pair id (token*2+slot) or -1 (dummy)
__device__ int   g_tok_sp[B_TOK * KTOP]; // pair id -> sorted slot
__device__ int   g_head_expert[8];

// ---------------- helpers ----------------
__device__ __forceinline__ float to_tf32(float f) {
    uint32_t u;
    asm("cvt.rna.tf32.f32 %0, %1;" : "=r"(u) : "f"(f));
    return __uint_as_float(u);
}

__device__ __forceinline__ void mma_tf32(float* c, const uint32_t* a, const uint32_t* b) {
    asm volatile(
        "mma.sync.aligned.m16n8k8.row.col.f32.tf32.tf32.f32 "
        "{%0,%1,%2,%3},{%4,%5,%6,%7},{%8,%9},{%0,%1,%2,%3};"
        : "+f"(c[0]), "+f"(c[1]), "+f"(c[2]), "+f"(c[3])
        : "r"(a[0]), "r"(a[1]), "r"(a[2]), "r"(a[3]), "r"(b[0]), "r"(b[1]));
}

// ---------------- kernel 1: concat ----------------
__global__ void k_concat(const float* __restrict__ z, const float* __restrict__ a) {
    int idx = blockIdx.x * 256 + threadIdx.x;
    int dd = idx & 127;
    int row = idx >> 7;
    g_x[idx] = (dd < DZ) ? z[row * DZ + dd] : a[row * DA + (dd - DZ)];
}

// ---------------- kernel 2: router ----------------
__global__ __launch_bounds__(256) void k_router(const float* __restrict__ w_gate,
                                                float* __restrict__ gates_out) {
    __shared__ float red[256 * 8];
    int b = blockIdx.x, tid = threadIdx.x;
    float p[8];
#pragma unroll
    for (int e = 0; e < 8; e++) p[e] = 0.f;
    const float* xb = g_x + (size_t)b * ND;
    for (int k = tid; k < ND; k += 256) {
        float xv = xb[k];
        const float4* wg = reinterpret_cast<const float4*>(w_gate + (size_t)k * 8);
        float4 w0 = wg[0], w1 = wg[1];
        p[0] = fmaf(xv, w0.x, p[0]); p[1] = fmaf(xv, w0.y, p[1]);
        p[2] = fmaf(xv, w0.z, p[2]); p[3] = fmaf(xv, w0.w, p[3]);
        p[4] = fmaf(xv, w1.x, p[4]); p[5] = fmaf(xv, w1.y, p[5]);
        p[6] = fmaf(xv, w1.z, p[6]); p[7] = fmaf(xv, w1.w, p[7]);
    }
#pragma unroll
    for (int e = 0; e < 8; e++) red[tid * 8 + e] = p[e];
    __syncthreads();
    for (int s = 128; s > 0; s >>= 1) {
        if (tid < s) {
#pragma unroll
            for (int e = 0; e < 8; e++) red[tid * 8 + e] += red[(tid + s) * 8 + e];
        }
        __syncthreads();
    }
    if (tid == 0) {
        float l[8];
#pragma unroll
        for (int e = 0; e < 8; e++) l[e] = red[e];
        int i0 = 0; float v0 = l[0];
#pragma unroll
        for (int e = 1; e < 8; e++) if (l[e] > v0) { v0 = l[e]; i0 = e; }
        int i1 = -1; float v1 = -3.4e38f;
#pragma unroll
        for (int e = 0; e < 8; e++) if (e != i0 && l[e] > v1) { v1 = l[e]; i1 = e; }
        float e1 = expf(v1 - v0);
        float inv = 1.f / (1.f + e1);
        float g0 = inv, g1v = e1 * inv;
#pragma unroll
        for (int e = 0; e < 8; e++)
            gates_out[b * 8 + e] = (e == i0) ? g0 : ((e == i1) ? g1v : 0.f);
        g_topidx[b * 2] = i0;  g_topidx[b * 2 + 1] = i1;
        g_topgate[b * 2] = g0; g_topgate[b * 2 + 1] = g1v;
        float s = 0.f;
#pragma unroll
        for (int e = 0; e < 8; e++) s += expf(l[e] - v0);
        g_lse[b] = v0 + logf(s);
    }
}

// ---------------- kernel 3: deterministic counting sort by expert ----------------
__global__ void k_sort() {
    __shared__ int cnt[8], off[8];
    int t = threadIdx.x;
    if (t < 8) {
        int c = 0;
        for (int p = 0; p < B_TOK * 2; p++) if (g_topidx[p] == t) c++;
        cnt[t] = c;
        g_head_expert[t] = 0;
    }
    __syncthreads();
    if (t == 0) {
        int o = 0, g = 0;
        for (int e = 0; e < 8; e++) {
            off[e] = o;
            int pc = (cnt[e] + 3) & ~3;
            int ngr = pc >> 2;
            for (int i = 0; i < ngr; i++) g_grp_expert[g++] = e;
            o += pc;
        }
        g_ngroups = g;
        g_npad = o;
    }
    __syncthreads();
    if (t < 8) {
        int pos = off[t];
        for (int p = 0; p < B_TOK * 2; p++)
            if (g_topidx[p] == t) { g_sp_pair[pos] = p; g_tok_sp[p] = pos; pos++; }
        int pe = off[t] + ((cnt[t] + 3) & ~3);
        for (; pos < pe; pos++) g_sp_pair[pos] = -1;
    }
}

// ---------------- generic tf32 batched GEMM ----------------
// C[128 rows, 128-col chunk] per block. 8 warps; warp owns 2 m-tiles x 8 n-tiles.
// SRC: 0=gather x by token (qkv), 1=g_ao, 4=g_y(head)
// DST: 0=g_qkv, 1=g_o, 4=g_hid
template<int KD, bool RELU, int SRC, int DST, bool HEAD>
__global__ __launch_bounds__(256) void k_gemm(const float* __restrict__ W,
                                              const float* __restrict__ bias,
                                              int Ntot) {
    int g = blockIdx.x;
    int ng = HEAD ? 8 : g_ngroups;
    if (g >= ng) return;
    int e = HEAD ? 0 : g_grp_expert[g];
    int n0 = blockIdx.y * 128;
    int tid = threadIdx.x, lane = tid & 31, w = tid >> 5;

    __shared__ float sA[128 * 36];
    __shared__ float sB[128 * 36];
    __shared__ const float* s_ab[4];

    if (tid < 4) {
        const float* ab;
        if (SRC == 0) {
            int pr = g_sp_pair[g * 4 + tid];
            int tok = (pr >= 0) ? (pr >> 1) : 0;
            ab = g_x + (size_t)tok * ND;
        } else {
            const float* base = (SRC == 1) ? g_ao : g_y;
            ab = base + (size_t)(g * 4 + tid) * 32 * KD;
        }
        s_ab[tid] = ab;
    }
    __syncthreads();

    const float* wb = W + (size_t)e * Ntot * KD + (size_t)n0 * KD;

    float acc[2][8][4];
#pragma unroll
    for (int i = 0; i < 2; i++)
#pragma unroll
        for (int j = 0; j < 8; j++)
#pragma unroll
            for (int k = 0; k < 4; k++) acc[i][j][k] = 0.f;

    int mt_base = (w & 3) * 2;
    int nt_base = (w >> 2) * 8;

    for (int kc = 0; kc < KD; kc += 32) {
#pragma unroll
        for (int it = 0; it < 4; it++) {
            int i = tid + it * 256;
            int r = i >> 3, q = (i & 7) * 4;
            float4 v = *reinterpret_cast<const float4*>(s_ab[r >> 5] + (size_t)(r & 31) * KD + kc + q);
            v.x = to_tf32(v.x); v.y = to_tf32(v.y); v.z = to_tf32(v.z); v.w = to_tf32(v.w);
            *reinterpret_cast<float4*>(sA + r * 36 + q) = v;
        }
#pragma unroll
        for (int it = 0; it < 4; it++) {
            int i = tid + it * 256;
            int r = i >> 3, q = (i & 7) * 4;
            float4 v = *reinterpret_cast<const float4*>(wb + (size_t)r * KD + kc + q);
            v.x = to_tf32(v.x); v.y = to_tf32(v.y); v.z = to_tf32(v.z); v.w = to_tf32(v.w);
            *reinterpret_cast<float4*>(sB + r * 36 + q) = v;
        }
        __syncthreads();
#pragma unroll
        for (int ks = 0; ks < 4; ks++) {
            int col = ks * 8 + (lane & 3);
            uint32_t a[2][4];
#pragma unroll
            for (int mt = 0; mt < 2; mt++) {
                int r0 = (mt_base + mt) * 16 + (lane >> 2);
                a[mt][0] = __float_as_uint(sA[r0 * 36 + col]);
                a[mt][1] = __float_as_uint(sA[(r0 + 8) * 36 + col]);
                a[mt][2] = __float_as_uint(sA[r0 * 36 + col + 4]);
                a[mt][3] = __float_as_uint(sA[(r0 + 8) * 36 + col + 4]);
            }
#pragma unroll
            for (int nt = 0; nt < 8; nt++) {
                int nr = (nt_base + nt) * 8 + (lane >> 2);
                uint32_t b[2];
                b[0] = __float_as_uint(sB[nr * 36 + col]);
                b[1] = __float_as_uint(sB[nr * 36 + col + 4]);
                mma_tf32(acc[0][nt], a[0], b);
                mma_tf32(acc[1][nt], a[1], b);
            }
        }
        __syncthreads();
    }

    float* Cb = (DST == 0) ? g_qkv : (DST == 1) ? g_o : g_hid;
#pragma unroll
    for (int mt = 0; mt < 2; mt++) {
        int r0 = (mt_base + mt) * 16 + (lane >> 2);
        int r1 = r0 + 8;
#pragma unroll
        for (int nt = 0; nt < 8; nt++) {
            int nc = n0 + (nt_base + nt) * 8 + 2 * (lane & 3);
            float2 bv = *reinterpret_cast<const float2*>(bias + (size_t)e * Ntot + nc);
            float2 o0, o1;
            o0.x = acc[mt][nt][0] + bv.x; o0.y = acc[mt][nt][1] + bv.y;
            o1.x = acc[mt][nt][2] + bv.x; o1.y = acc[mt][nt][3] + bv.y;
            if (RELU) {
                o0.x = fmaxf(o0.x, 0.f); o0.y = fmaxf(o0.y, 0.f);
                o1.x = fmaxf(o1.x, 0.f); o1.y = fmaxf(o1.y, 0.f);
            }
            size_t row0 = (size_t)g * 128 + r0;
            size_t row1 = (size_t)g * 128 + r1;
            *reinterpret_cast<float2*>(Cb + row0 * Ntot + nc) = o0;
            *reinterpret_cast<float2*>(Cb + row1 * Ntot + nc) = o1;
        }
    }
}

// ---------------- fused FFN: f2 = relu(h @ W1^T + b1) @ W2^T + b2 ----------------
// Block = (group, half): 64 rows x 128 out. Loops over 8 F-chunks of 128;
// stage1 computes relu chunk into smem (tf32), stage2 accumulates into regs.
#define FFN_SA   (64 * 36)
#define FFN_SW   (128 * 36)
#define FFN_SF   (64 * 132)
#define FFN_SMEM_BYTES ((FFN_SA + FFN_SW + FFN_SF) * 4)

__global__ __launch_bounds__(256) void k_ffn(const float* __restrict__ W1,
                                             const float* __restrict__ B1,
                                             const float* __restrict__ W2,
                                             const float* __restrict__ B2) {
    int g = blockIdx.x;
    if (g >= g_ngroups) return;
    int half = blockIdx.y;
    int e = g_grp_expert[g];
    int tid = threadIdx.x, lane = tid & 31, w = tid >> 5;

    extern __shared__ float sm[];
    float* sA = sm;
    float* sW = sm + FFN_SA;
    float* sF = sm + FFN_SA + FFN_SW;

    const float* hb  = g_h + ((size_t)g * 128 + half * 64) * 128;
    const float* w1b = W1 + (size_t)e * 1024 * 128;
    const float* w2b = W2 + (size_t)e * 128 * 1024;

    int mt = (w & 3);              // 16-row m tile
    int nt_base = (w >> 2) * 8;    // 8 n-tiles of 8

    float acc2[8][4];
#pragma unroll
    for (int j = 0; j < 8; j++)
#pragma unroll
        for (int k = 0; k < 4; k++) acc2[j][k] = 0.f;

    for (int c = 0; c < 8; c++) {
        float acc1[8][4];
#pragma unroll
        for (int j = 0; j < 8; j++)
#pragma unroll
            for (int k = 0; k < 4; k++) acc1[j][k] = 0.f;

        for (int kc = 0; kc < 128; kc += 32) {
#pragma unroll
            for (int it = 0; it < 2; it++) {
                int i = tid + it * 256;
                int r = i >> 3, q = (i & 7) * 4;
                float4 v = *reinterpret_cast<const float4*>(hb + (size_t)r * 128 + kc + q);
                v.x = to_tf32(v.x); v.y = to_tf32(v.y); v.z = to_tf32(v.z); v.w = to_tf32(v.w);
                *reinterpret_cast<float4*>(sA + r * 36 + q) = v;
            }
#pragma unroll
            for (int it = 0; it < 4; it++) {
                int i = tid + it * 256;
                int r = i >> 3, q = (i & 7) * 4;
                float4 v = *reinterpret_cast<const float4*>(w1b + (size_t)(c * 128 + r) * 128 + kc + q);
                v.x = to_tf32(v.x); v.y = to_tf32(v.y); v.z = to_tf32(v.z); v.w = to_tf32(v.w);
                *reinterpret_cast<float4*>(sW + r * 36 + q) = v;
            }
            __syncthreads();
#pragma unroll
            for (int ks = 0; ks < 4; ks++) {
                int col = ks * 8 + (lane & 3);
                int r0 = mt * 16 + (lane >> 2);
                uint32_t a[4];
                a[0] = __float_as_uint(sA[r0 * 36 + col]);
                a[1] = __float_as_uint(sA[(r0 + 8) * 36 + col]);
                a[2] = __float_as_uint(sA[r0 * 36 + col + 4]);
                a[3] = __float_as_uint(sA[(r0 + 8) * 36 + col + 4]);
#pragma unroll
                for (int nt = 0; nt < 8; nt++) {
                    int nr = (nt_base + nt) * 8 + (lane >> 2);
                    uint32_t b[2];
                    b[0] = __float_as_uint(sW[nr * 36 + col]);
                    b[1] = __float_as_uint(sW[nr * 36 + col + 4]);
                    mma_tf32(acc1[nt], a, b);
                }
            }
            __syncthreads();
        }
        // relu + bias, tf32, write to sF
        {
            int r0 = mt * 16 + (lane >> 2);
#pragma unroll
            for (int nt = 0; nt < 8; nt++) {
                int nc = (nt_base + nt) * 8 + 2 * (lane & 3);
                float2 bv = *reinterpret_cast<const float2*>(B1 + (size_t)e * 1024 + c * 128 + nc);
                float2 o0, o1;
                o0.x = to_tf32(fmaxf(acc1[nt][0] + bv.x, 0.f));
                o0.y = to_tf32(fmaxf(acc1[nt][1] + bv.y, 0.f));
                o1.x = to_tf32(fmaxf(acc1[nt][2] + bv.x, 0.f));
                o1.y = to_tf32(fmaxf(acc1[nt][3] + bv.y, 0.f));
                *reinterpret_cast<float2*>(sF + r0 * 132 + nc) = o0;
                *reinterpret_cast<float2*>(sF + (r0 + 8) * 132 + nc) = o1;
            }
        }
        __syncthreads();
        // stage 2: acc2 += f1_chunk @ W2_chunk^T
        for (int kc2 = 0; kc2 < 128; kc2 += 32) {
#pragma unroll
            for (int it = 0; it < 4; it++) {
                int i = tid + it * 256;
                int r = i >> 3, q = (i & 7) * 4;
                float4 v = *reinterpret_cast<const float4*>(w2b + (size_t)r * 1024 + c * 128 + kc2 + q);
                v.x = to_tf32(v.x); v.y = to_tf32(v.y); v.z = to_tf32(v.z); v.w = to_tf32(v.w);
                *reinterpret_cast<float4*>(sW + r * 36 + q) = v;
            }
            __syncthreads();
#pragma unroll
            for (int ks = 0; ks < 4; ks++) {
                int col = ks * 8 + (lane & 3);
                int r0 = mt * 16 + (lane >> 2);
                uint32_t a[4];
                a[0] = __float_as_uint(sF[r0 * 132 + kc2 + col]);
                a[1] = __float_as_uint(sF[(r0 + 8) * 132 + kc2 + col]);
                a[2] = __float_as_uint(sF[r0 * 132 + kc2 + col + 4]);
                a[3] = __float_as_uint(sF[(r0 + 8) * 132 + kc2 + col + 4]);
#pragma unroll
                for (int nt = 0; nt < 8; nt++) {
                    int nr = (nt_base + nt) * 8 + (lane >> 2);
                    uint32_t b[2];
                    b[0] = __float_as_uint(sW[nr * 36 + col]);
                    b[1] = __float_as_uint(sW[nr * 36 + col + 4]);
                    mma_tf32(acc2[nt], a, b);
                }
            }
            __syncthreads();
        }
    }
    // epilogue
    {
        int r0 = mt * 16 + (lane >> 2);
        float* f2b = g_f2 + ((size_t)g * 128 + half * 64) * 128;
#pragma unroll
        for (int nt = 0; nt < 8; nt++) {
            int nc = (nt_base + nt) * 8 + 2 * (lane & 3);
            float2 bv = *reinterpret_cast<const float2*>(B2 + (size_t)e * 128 + nc);
            float2 o0, o1;
            o0.x = acc2[nt][0] + bv.x; o0.y = acc2[nt][1] + bv.y;
            o1.x = acc2[nt][2] + bv.x; o1.y = acc2[nt][3] + bv.y;
            *reinterpret_cast<float2*>(f2b + (size_t)r0 * 128 + nc) = o0;
            *reinterpret_cast<float2*>(f2b + (size_t)(r0 + 8) * 128 + nc) = o1;
        }
    }
}

// ---------------- attention (per pair, 4 warps = 4 heads) ----------------
__global__ __launch_bounds__(128) void k_attn() {
    int sp = blockIdx.x;
    if (sp >= g_npad) return;
    if (g_sp_pair[sp] < 0) return;
    __shared__ float s_kv[32 * 261];
    int tid = threadIdx.x, lane = tid & 31, h = tid >> 5;
    for (int i = tid; i < 32 * 256; i += 128) {
        int r = i >> 8, c = i & 255;
        s_kv[r * 261 + c] = g_qkv[((size_t)sp * 32 + r) * 384 + 128 + c];
    }
    __syncthreads();
    float kreg[32];
#pragma unroll
    for (int d = 0; d < 32; d++) kreg[d] = s_kv[lane * 261 + h * 32 + d];
    const float* qb = g_qkv + (size_t)sp * 32 * 384;
    for (int q = 0; q < 32; q++) {
        const float4* qp = reinterpret_cast<const float4*>(qb + q * 384 + h * 32);
        float sc = 0.f;
#pragma unroll
        for (int d4 = 0; d4 < 8; d4++) {
            float4 q4 = qp[d4];
            sc += q4.x * kreg[d4 * 4] + q4.y * kreg[d4 * 4 + 1]
                + q4.z * kreg[d4 * 4 + 2] + q4.w * kreg[d4 * 4 + 3];
        }
        sc *= 0.1767766952966369f;
        float m = sc;
#pragma unroll
        for (int off = 16; off > 0; off >>= 1)
            m = fmaxf(m, __shfl_xor_sync(0xffffffffu, m, off));
        float pr = expf(sc - m);
        float ss = pr;
#pragma unroll
        for (int off = 16; off > 0; off >>= 1)
            ss += __shfl_xor_sync(0xffffffffu, ss, off);
        float att = pr / ss;
        float o = 0.f;
#pragma unroll
        for (int kk = 0; kk < 32; kk++) {
            float av = __shfl_sync(0xffffffffu, att, kk);
            o = fmaf(av, s_kv[kk * 261 + 128 + h * 32 + lane], o);
        }
        g_ao[((size_t)sp * 32 + q) * 128 + h * 32 + lane] = o;
    }
}

// ---------------- LN1: h = LN(x + o) ----------------
__global__ __launch_bounds__(128) void k_ln1(const float* __restrict__ ln1_g,
                                             const float* __restrict__ ln1_b) {
    int sp = blockIdx.x;
    if (sp >= g_npad) return;
    int pr = g_sp_pair[sp];
    if (pr < 0) return;
    int token = pr >> 1;
    int e = g_topidx[pr];
    int tid = threadIdx.x, lane = tid & 31, w = tid >> 5;
    const float* g1 = ln1_g + e * 128;
    const float* b1 = ln1_b + e * 128;
    for (int rr = 0; rr < 8; rr++) {
        int r = w * 8 + rr;
        float v[4]; float sum = 0.f, sq = 0.f;
#pragma unroll
        for (int j = 0; j < 4; j++) {
            int c = lane + 32 * j;
            v[j] = g_x[(size_t)token * ND + r * 128 + c]
                 + g_o[((size_t)sp * 32 + r) * 128 + c];
            sum += v[j]; sq += v[j] * v[j];
        }
#pragma unroll
        for (int off = 16; off > 0; off >>= 1) {
            sum += __shfl_xor_sync(0xffffffffu, sum, off);
            sq  += __shfl_xor_sync(0xffffffffu, sq, off);
        }
        float mu = sum * (1.f / 128.f);
        float var = sq * (1.f / 128.f) - mu * mu;
        float rs = rsqrtf(var + 1e-5f);
#pragma unroll
        for (int j = 0; j < 4; j++) {
            int c = lane + 32 * j;
            g_h[((size_t)sp * 32 + r) * 128 + c] = (v[j] - mu) * rs * g1[c] + b1[c];
        }
    }
}

// ---------------- finish: y = sum_slots gate * LN2(h + f2) ----------------
__global__ __launch_bounds__(128) void k_finish(const float* __restrict__ ln2_g,
                                                const float* __restrict__ ln2_b) {
    int t = blockIdx.x;
    int tid = threadIdx.x, lane = tid & 31, w = tid >> 5;
    float y[8][4];
#pragma unroll
    for (int rr = 0; rr < 8; rr++)
#pragma unroll
        for (int j = 0; j < 4; j++) y[rr][j] = 0.f;

    for (int slot = 0; slot < 2; slot++) {
        int pr = t * 2 + slot;
        int sp = g_tok_sp[pr];
        int e = g_topidx[pr];
        float gate = g_topgate[pr];
        const float* g2 = ln2_g + e * 128;
        const float* b2 = ln2_b + e * 128;
        for (int rr = 0; rr < 8; rr++) {
            int r = w * 8 + rr;
            float v[4]; float sum = 0.f, sq = 0.f;
#pragma unroll
            for (int j = 0; j < 4; j++) {
                int c = lane + 32 * j;
                v[j] = g_h[((size_t)sp * 32 + r) * 128 + c]
                     + g_f2[((size_t)sp * 32 + r) * 128 + c];
                sum += v[j]; sq += v[j] * v[j];
            }
#pragma unroll
            for (int off = 16; off > 0; off >>= 1) {
                sum += __shfl_xor_sync(0xffffffffu, sum, off);
                sq  += __shfl_xor_sync(0xffffffffu, sq, off);
            }
            float mu = sum * (1.f / 128.f);
            float var = sq * (1.f / 128.f) - mu * mu;
            float rs = rsqrtf(var + 1e-5f);
#pragma unroll
            for (int j = 0; j < 4; j++) {
                int c = lane + 32 * j;
                y[rr][j] += gate * ((v[j] - mu) * rs * g2[c] + b2[c]);
            }
        }
    }
    for (int rr = 0; rr < 8; rr++) {
        int r = w * 8 + rr;
#pragma unroll
        for (int j = 0; j < 4; j++) {
            int c = lane + 32 * j;
            g_y[(size_t)t * ND + r * 128 + c] = y[rr][j];
        }
    }
}

// ---------------- head GEMV2 ----------------
__global__ void k_head2(const float* __restrict__ hw2, const float* __restrict__ hb2,
                        float* __restrict__ out_r) {
    int b = blockIdx.x;
    int j = threadIdx.x >> 5;
    int lane = threadIdx.x & 31;
    const float* hb = g_hid + (size_t)b * HH;
    const float* w = hw2 + (size_t)j * HH;
    float s = 0.f;
    for (int k = lane; k < HH; k += 32) s = fmaf(hb[k], w[k], s);
#pragma unroll
    for (int off = 16; off > 0; off >>= 1) s += __shfl_xor_sync(0xffffffffu, s, off);
    if (lane == 0) out_r[b * NR + j] = s + hb2[j];
}

// ---------------- loss ----------------
__global__ void k_loss(const float* __restrict__ gates, float* __restrict__ out_loss) {
    __shared__ float s_imp[8][32], s_ld[8][32], s_lse[256];
    int t = threadIdx.x;
    int e = t & 7, c = t >> 3;
    float imp = 0.f, ld = 0.f;
    for (int b = c; b < B_TOK; b += 32) {
        float g = gates[b * 8 + e];
        imp += g;
        if (g > 0.f) ld += 1.f;
    }
    s_imp[e][c] = imp; s_ld[e][c] = ld;
    float ls = 0.f;
    for (int b = t; b < B_TOK; b += 256) ls += g_lse[b];
    s_lse[t] = ls;
    __syncthreads();
    for (int s = 128; s > 0; s >>= 1) {
        if (t < s) s_lse[t] += s_lse[t + s];
        __syncthreads();
    }
    if (t == 0) {
        float I[8], L[8];
        float mi = 0.f, ml = 0.f;
        for (int e2 = 0; e2 < 8; e2++) {
            float si = 0.f, sl = 0.f;
            for (int c2 = 0; c2 < 32; c2++) { si += s_imp[e2][c2]; sl += s_ld[e2][c2]; }
            I[e2] = si; L[e2] = sl; mi += si; ml += sl;
        }
        mi *= 0.125f; ml *= 0.125f;
        float vi = 0.f, vl = 0.f;
        for (int e2 = 0; e2 < 8; e2++) {
            vi += (I[e2] - mi) * (I[e2] - mi);
            vl += (L[e2] - ml) * (L[e2] - ml);
        }
        vi /= 7.f; vl /= 7.f;
        float loss = vi / (mi * mi + 1e-10f) + vl / (ml * ml + 1e-10f)
                   + s_lse[0] * (1.f / (float)B_TOK);
        *out_loss = loss;
    }
}

// ---------------- launch ----------------
extern "C" void kernel_launch(void* const* d_in, const int* in_sizes, int n_in,
                              void* d_out, int out_size) {
    const float* z      = (const float*)d_in[0];
    const float* a      = (const float*)d_in[1];
    const float* w_gate = (const float*)d_in[2];
    const float* w_in   = (const float*)d_in[3];
    const float* b_in   = (const float*)d_in[4];
    const float* w_out  = (const float*)d_in[5];
    const float* b_out  = (const float*)d_in[6];
    const float* ln1_g  = (const float*)d_in[7];
    const float* ln1_b  = (const float*)d_in[8];
    const float* w1     = (const float*)d_in[9];
    const float* b1     = (const float*)d_in[10];
    const float* w2     = (const float*)d_in[11];
    const float* b2     = (const float*)d_in[12];
    const float* ln2_g  = (const float*)d_in[13];
    const float* ln2_b  = (const float*)d_in[14];
    const float* hw1    = (const float*)d_in[15];
    const float* hb1    = (const float*)d_in[16];
    const float* hw2    = (const float*)d_in[17];
    const float* hb2    = (const float*)d_in[18];

    float* out       = (float*)d_out;
    float* gates_out = out + B_TOK * NR;
    float* loss_out  = out + B_TOK * NR + B_TOK * NEXP;

    static int ffn_attr_set = 0;
    if (!ffn_attr_set) {
        cudaFuncSetAttribute(k_ffn, cudaFuncAttributeMaxDynamicSharedMemorySize,
                             FFN_SMEM_BYTES);
        ffn_attr_set = 1;
    }

    k_concat<<<(B_TOK * ND) / 256, 256>>>(z, a);
    k_router<<<B_TOK, 256>>>(w_gate, gates_out);
    k_sort<<<1, 32>>>();

    // qkv = x @ w_in^T + b_in       [pairs*32, 384]
    k_gemm<128, false, 0, 0, false><<<dim3(GROUP_MAX, 3), 256>>>(w_in, b_in, 384);
    k_attn<<<PAIR_MAX, 128>>>();
    // o = ao @ w_out^T + b_out      [pairs*32, 128]
    k_gemm<128, false, 1, 1, false><<<dim3(GROUP_MAX, 1), 256>>>(w_out, b_out, 128);
    k_ln1<<<PAIR_MAX, 128>>>(ln1_g, ln1_b);
    // f2 = relu(h @ w1^T + b1) @ w2^T + b2   (fused)
    k_ffn<<<dim3(GROUP_MAX, 2), 256, FFN_SMEM_BYTES>>>(w1, b1, w2, b2);
    k_finish<<<B_TOK, 128>>>(ln2_g, ln2_b);
    // hid = relu(y @ hw1^T + hb1)   [1024, 512]
    k_gemm<4096, true, 4, 4, true><<<dim3(8, 4), 256>>>(hw1, hb1, 512);
    k_head2<<<B_TOK, 128>>>(hw2, hb2, out);
    k_loss<<<1, 256>>>(gates_out, loss_out);
}

// round 8
// speedup vs baseline: 3.2634x; 1.3400x over previous
#include <cuda_runtime.h>
#include <cuda_bf16.h>
#include <cstdint>

// ---------------- problem constants ----------------
#define B_TOK   1024
#define NA      32
#define DZ      96
#define DA      32
#define DMODEL  128
#define ND      4096      // NA*DMODEL
#define NEXP    8
#define FF      1024
#define HH      512
#define NR      4
#define KTOP    2

#define PAIR_MAX  2072
#define GROUP_MAX 518

// ---------------- scratch ----------------
__device__ float g_x [B_TOK * ND];               // concat(z,a), UNROUNDED (router + LN1 residual)
__device__ float g_xt[B_TOK * ND];               // tf32-rounded copy (GEMM A operand)
__device__ float g_y [B_TOK * ND];
__device__ float g_qkv[(size_t)PAIR_MAX * 32 * 384];
__device__ float g_ao [(size_t)PAIR_MAX * 32 * 128];
__device__ float g_o  [(size_t)PAIR_MAX * 32 * 128];
__device__ float g_h  [(size_t)PAIR_MAX * 32 * 128];
__device__ float g_f2 [(size_t)PAIR_MAX * 32 * 128];
__device__ float g_hid[B_TOK * HH];
__device__ float g_hp [4 * B_TOK * HH];
__device__ float g_lse[B_TOK];
__device__ int   g_topidx[B_TOK * KTOP];
__device__ float g_topgate[B_TOK * KTOP];

// tf32-rounded weight copies (ONLY referenced from device code!)
__device__ float g_wint [NEXP * 384 * 128];
__device__ float g_woutt[NEXP * 128 * 128];
__device__ float g_w1t  [NEXP * 1024 * 128];
__device__ float g_w2t  [NEXP * 128 * 1024];
__device__ float g_hw1t [HH * ND];

__device__ int   g_ngroups;
__device__ int   g_npad;
__device__ int   g_grp_expert[GROUP_MAX];
__device__ int   g_sp_pair[PAIR_MAX];
__device__ int   g_tok_sp[B_TOK * KTOP];

// ---------------- helpers ----------------
__device__ __forceinline__ float to_tf32(float f) {
    uint32_t u;
    asm("cvt.rna.tf32.f32 %0, %1;" : "=r"(u) : "f"(f));
    return __uint_as_float(u);
}

__device__ __forceinline__ void mma_tf32(float* c, const uint32_t* a, const uint32_t* b) {
    asm volatile(
        "mma.sync.aligned.m16n8k8.row.col.f32.tf32.tf32.f32 "
        "{%0,%1,%2,%3},{%4,%5,%6,%7},{%8,%9},{%0,%1,%2,%3};"
        : "+f"(c[0]), "+f"(c[1]), "+f"(c[2]), "+f"(c[3])
        : "r"(a[0]), "r"(a[1]), "r"(a[2]), "r"(a[3]), "r"(b[0]), "r"(b[1]));
}

__device__ __forceinline__ void cp_async16(uint32_t saddr, const void* gaddr) {
    asm volatile("cp.async.cg.shared.global [%0], [%1], 16;\n" :: "r"(saddr), "l"(gaddr));
}
#define CP_COMMIT() asm volatile("cp.async.commit_group;\n")
#define CP_WAIT1()  asm volatile("cp.async.wait_group 1;\n")
#define CP_WAIT0()  asm volatile("cp.async.wait_group 0;\n")

// ---------------- weight rounding prep ----------------
#define RW0 (NEXP * 384 * 128)
#define RW1 (RW0 + NEXP * 128 * 128)
#define RW2 (RW1 + NEXP * 1024 * 128)
#define RW3 (RW2 + NEXP * 128 * 1024)
#define RW4 (RW3 + HH * ND)
__global__ void k_round(const float* __restrict__ w_in, const float* __restrict__ w_out,
                        const float* __restrict__ w1, const float* __restrict__ w2,
                        const float* __restrict__ hw1) {
    int i = blockIdx.x * 256 + threadIdx.x;
    if (i < RW0)      g_wint[i]        = to_tf32(w_in[i]);
    else if (i < RW1) g_woutt[i - RW0] = to_tf32(w_out[i - RW0]);
    else if (i < RW2) g_w1t[i - RW1]   = to_tf32(w1[i - RW1]);
    else if (i < RW3) g_w2t[i - RW2]   = to_tf32(w2[i - RW2]);
    else if (i < RW4) g_hw1t[i - RW3]  = to_tf32(hw1[i - RW3]);
}

// ---------------- concat: unrounded + rounded copies ----------------
__global__ void k_concat(const float* __restrict__ z, const float* __restrict__ a) {
    int idx = blockIdx.x * 256 + threadIdx.x;
    int dd = idx & 127;
    int row = idx >> 7;
    float v = (dd < DZ) ? z[row * DZ + dd] : a[row * DA + (dd - DZ)];
    g_x[idx]  = v;
    g_xt[idx] = to_tf32(v);
}

// ---------------- router (reads UNROUNDED x: exact top-k selection) ----------------
__global__ __launch_bounds__(256) void k_router(const float* __restrict__ w_gate,
                                                float* __restrict__ gates_out) {
    __shared__ float red[256 * 8];
    int b = blockIdx.x, tid = threadIdx.x;
    float p[8];
#pragma unroll
    for (int e = 0; e < 8; e++) p[e] = 0.f;
    const float* xb = g_x + (size_t)b * ND;
    for (int k = tid; k < ND; k += 256) {
        float xv = xb[k];
        const float4* wg = reinterpret_cast<const float4*>(w_gate + (size_t)k * 8);
        float4 w0 = wg[0], w1 = wg[1];
        p[0] = fmaf(xv, w0.x, p[0]); p[1] = fmaf(xv, w0.y, p[1]);
        p[2] = fmaf(xv, w0.z, p[2]); p[3] = fmaf(xv, w0.w, p[3]);
        p[4] = fmaf(xv, w1.x, p[4]); p[5] = fmaf(xv, w1.y, p[5]);
        p[6] = fmaf(xv, w1.z, p[6]); p[7] = fmaf(xv, w1.w, p[7]);
    }
#pragma unroll
    for (int e = 0; e < 8; e++) red[tid * 8 + e] = p[e];
    __syncthreads();
    for (int s = 128; s > 0; s >>= 1) {
        if (tid < s) {
#pragma unroll
            for (int e = 0; e < 8; e++) red[tid * 8 + e] += red[(tid + s) * 8 + e];
        }
        __syncthreads();
    }
    if (tid == 0) {
        float l[8];
#pragma unroll
        for (int e = 0; e < 8; e++) l[e] = red[e];
        int i0 = 0; float v0 = l[0];
#pragma unroll
        for (int e = 1; e < 8; e++) if (l[e] > v0) { v0 = l[e]; i0 = e; }
        int i1 = -1; float v1 = -3.4e38f;
#pragma unroll
        for (int e = 0; e < 8; e++) if (e != i0 && l[e] > v1) { v1 = l[e]; i1 = e; }
        float e1 = expf(v1 - v0);
        float inv = 1.f / (1.f + e1);
        float g0 = inv, g1v = e1 * inv;
#pragma unroll
        for (int e = 0; e < 8; e++)
            gates_out[b * 8 + e] = (e == i0) ? g0 : ((e == i1) ? g1v : 0.f);
        g_topidx[b * 2] = i0;  g_topidx[b * 2 + 1] = i1;
        g_topgate[b * 2] = g0; g_topgate[b * 2 + 1] = g1v;
        float s = 0.f;
#pragma unroll
        for (int e = 0; e < 8; e++) s += expf(l[e] - v0);
        g_lse[b] = v0 + logf(s);
    }
}

// ---------------- counting sort ----------------
__global__ void k_sort() {
    __shared__ int cnt[8], off[8];
    int t = threadIdx.x;
    if (t < 8) {
        int c = 0;
        for (int p = 0; p < B_TOK * 2; p++) if (g_topidx[p] == t) c++;
        cnt[t] = c;
    }
    __syncthreads();
    if (t == 0) {
        int o = 0, g = 0;
        for (int e = 0; e < 8; e++) {
            off[e] = o;
            int pc = (cnt[e] + 3) & ~3;
            for (int i = 0; i < (pc >> 2); i++) g_grp_expert[g++] = e;
            o += pc;
        }
        g_ngroups = g;
        g_npad = o;
    }
    __syncthreads();
    if (t < 8) {
        int pos = off[t];
        for (int p = 0; p < B_TOK * 2; p++)
            if (g_topidx[p] == t) { g_sp_pair[pos] = p; g_tok_sp[p] = pos; pos++; }
        int pe = off[t] + ((cnt[t] + 3) & ~3);
        for (; pos < pe; pos++) g_sp_pair[pos] = -1;
    }
}

// ---------------- cp.async stage helpers ----------------
__device__ __forceinline__ void gemm_issue(uint32_t smu, int buf, int kc,
                                           const float* const* s_ab,
                                           const float* wb, int tid) {
#pragma unroll
    for (int it = 0; it < 4; it++) {
        int i = tid + it * 256;
        int r = i >> 3, q = (i & 7) * 4;
        cp_async16(smu + (uint32_t)(buf * 4608 + r * 36 + q) * 4,
                   s_ab[r >> 5] + (size_t)(r & 31) * 128 + kc + q);
        cp_async16(smu + (uint32_t)(9216 + buf * 4608 + r * 36 + q) * 4,
                   wb + (size_t)r * 128 + kc + q);
    }
    CP_COMMIT();
}

__device__ __forceinline__ void head_issue(uint32_t smu, int buf, int kc,
                                           const float* Ab, const float* Bb, int tid) {
#pragma unroll
    for (int it = 0; it < 4; it++) {
        int i = tid + it * 256;
        int r = i >> 3, q = (i & 7) * 4;
        cp_async16(smu + (uint32_t)(buf * 4608 + r * 36 + q) * 4,
                   Ab + (size_t)r * ND + kc + q);
        cp_async16(smu + (uint32_t)(9216 + buf * 4608 + r * 36 + q) * 4,
                   Bb + (size_t)r * ND + kc + q);
    }
    CP_COMMIT();
}

// ---------------- tf32 batched GEMM (cp.async double-buffered) ----------------
#define GEMM_SMEM_BYTES 73728
template<int SRC, int DST>
__global__ __launch_bounds__(256) void k_gemm(const float* __restrict__ bias, int Ntot) {
    int g = blockIdx.x;
    if (g >= g_ngroups) return;
    int e = g_grp_expert[g];
    int n0 = blockIdx.y * 128;
    int tid = threadIdx.x, lane = tid & 31, w = tid >> 5;

    extern __shared__ float sm[];
    uint32_t smu = (uint32_t)__cvta_generic_to_shared(sm);
    __shared__ const float* s_ab[4];
    if (tid < 4) {
        const float* ab;
        if (SRC == 0) {
            int pr = g_sp_pair[g * 4 + tid];
            int tok = (pr >= 0) ? (pr >> 1) : 0;
            ab = g_xt + (size_t)tok * ND;      // tf32-rounded copy
        } else {
            ab = g_ao + (size_t)(g * 4 + tid) * 32 * 128;
        }
        s_ab[tid] = ab;
    }
    __syncthreads();

    const float* W = (SRC == 0) ? g_wint : g_woutt;
    const float* wb = W + (size_t)e * Ntot * 128 + (size_t)n0 * 128;

    float acc[2][8][4];
#pragma unroll
    for (int i = 0; i < 2; i++)
#pragma unroll
        for (int j = 0; j < 8; j++)
#pragma unroll
            for (int k = 0; k < 4; k++) acc[i][j][k] = 0.f;

    int mt_base = (w & 3) * 2;
    int nt_base = (w >> 2) * 8;

    gemm_issue(smu, 0, 0, s_ab, wb, tid);
    for (int c = 0; c < 4; c++) {
        if (c + 1 < 4) { gemm_issue(smu, (c + 1) & 1, (c + 1) * 32, s_ab, wb, tid); CP_WAIT1(); }
        else CP_WAIT0();
        __syncthreads();
        const float* sA = sm + (c & 1) * 4608;
        const float* sB = sm + 9216 + (c & 1) * 4608;
#pragma unroll
        for (int ks = 0; ks < 4; ks++) {
            int col = ks * 8 + (lane & 3);
            uint32_t a[2][4];
#pragma unroll
            for (int mt = 0; mt < 2; mt++) {
                int r0 = (mt_base + mt) * 16 + (lane >> 2);
                a[mt][0] = __float_as_uint(sA[r0 * 36 + col]);
                a[mt][1] = __float_as_uint(sA[(r0 + 8) * 36 + col]);
                a[mt][2] = __float_as_uint(sA[r0 * 36 + col + 4]);
                a[mt][3] = __float_as_uint(sA[(r0 + 8) * 36 + col + 4]);
            }
#pragma unroll
            for (int nt = 0; nt < 8; nt++) {
                int nr = (nt_base + nt) * 8 + (lane >> 2);
                uint32_t b[2];
                b[0] = __float_as_uint(sB[nr * 36 + col]);
                b[1] = __float_as_uint(sB[nr * 36 + col + 4]);
                mma_tf32(acc[0][nt], a[0], b);
                mma_tf32(acc[1][nt], a[1], b);
            }
        }
        __syncthreads();
    }

    float* Cb = (DST == 0) ? g_qkv : g_o;
#pragma unroll
    for (int mt = 0; mt < 2; mt++) {
        int r0 = (mt_base + mt) * 16 + (lane >> 2);
        int r1 = r0 + 8;
#pragma unroll
        for (int nt = 0; nt < 8; nt++) {
            int nc = n0 + (nt_base + nt) * 8 + 2 * (lane & 3);
            float2 bv = *reinterpret_cast<const float2*>(bias + (size_t)e * Ntot + nc);
            float2 o0, o1;
            o0.x = acc[mt][nt][0] + bv.x; o0.y = acc[mt][nt][1] + bv.y;
            o1.x = acc[mt][nt][2] + bv.x; o1.y = acc[mt][nt][3] + bv.y;
            *reinterpret_cast<float2*>(Cb + ((size_t)g * 128 + r0) * Ntot + nc) = o0;
            *reinterpret_cast<float2*>(Cb + ((size_t)g * 128 + r1) * Ntot + nc) = o1;
        }
    }
}

// ---------------- head1: split-K tf32 GEMM (cp.async double-buffered) ----------------
__global__ __launch_bounds__(256) void k_head1() {
    int bm = blockIdx.x, bn = blockIdx.y, ks4 = blockIdx.z;
    int tid = threadIdx.x, lane = tid & 31, w = tid >> 5;

    extern __shared__ float sm[];
    uint32_t smu = (uint32_t)__cvta_generic_to_shared(sm);

    const float* Ab = g_y + (size_t)(bm * 128) * ND + ks4 * 1024;
    const float* Bb = g_hw1t + (size_t)(bn * 128) * ND + ks4 * 1024;

    float acc[2][8][4];
#pragma unroll
    for (int i = 0; i < 2; i++)
#pragma unroll
        for (int j = 0; j < 8; j++)
#pragma unroll
            for (int k = 0; k < 4; k++) acc[i][j][k] = 0.f;

    int mt_base = (w & 3) * 2;
    int nt_base = (w >> 2) * 8;

    head_issue(smu, 0, 0, Ab, Bb, tid);
    for (int c = 0; c < 32; c++) {
        if (c + 1 < 32) { head_issue(smu, (c + 1) & 1, (c + 1) * 32, Ab, Bb, tid); CP_WAIT1(); }
        else CP_WAIT0();
        __syncthreads();
        const float* sA = sm + (c & 1) * 4608;
        const float* sB = sm + 9216 + (c & 1) * 4608;
#pragma unroll
        for (int ks = 0; ks < 4; ks++) {
            int col = ks * 8 + (lane & 3);
            uint32_t a[2][4];
#pragma unroll
            for (int mt = 0; mt < 2; mt++) {
                int r0 = (mt_base + mt) * 16 + (lane >> 2);
                a[mt][0] = __float_as_uint(sA[r0 * 36 + col]);
                a[mt][1] = __float_as_uint(sA[(r0 + 8) * 36 + col]);
                a[mt][2] = __float_as_uint(sA[r0 * 36 + col + 4]);
                a[mt][3] = __float_as_uint(sA[(r0 + 8) * 36 + col + 4]);
            }
#pragma unroll
            for (int nt = 0; nt < 8; nt++) {
                int nr = (nt_base + nt) * 8 + (lane >> 2);
                uint32_t b[2];
                b[0] = __float_as_uint(sB[nr * 36 + col]);
                b[1] = __float_as_uint(sB[nr * 36 + col + 4]);
                mma_tf32(acc[0][nt], a[0], b);
                mma_tf32(acc[1][nt], a[1], b);
            }
        }
        __syncthreads();
    }

    float* dst = g_hp + ((size_t)ks4 * B_TOK + bm * 128) * HH + bn * 128;
#pragma unroll
    for (int mt = 0; mt < 2; mt++) {
        int r0 = (mt_base + mt) * 16 + (lane >> 2);
        int r1 = r0 + 8;
#pragma unroll
        for (int nt = 0; nt < 8; nt++) {
            int nc = (nt_base + nt) * 8 + 2 * (lane & 3);
            float2 o0, o1;
            o0.x = acc[mt][nt][0]; o0.y = acc[mt][nt][1];
            o1.x = acc[mt][nt][2]; o1.y = acc[mt][nt][3];
            *reinterpret_cast<float2*>(dst + (size_t)r0 * HH + nc) = o0;
            *reinterpret_cast<float2*>(dst + (size_t)r1 * HH + nc) = o1;
        }
    }
}

__global__ void k_head1red(const float* __restrict__ hb1) {
    int i = blockIdx.x * 256 + threadIdx.x;
    int n = i & (HH - 1);
    float s = g_hp[i] + g_hp[B_TOK * HH + i] + g_hp[2 * B_TOK * HH + i]
            + g_hp[3 * B_TOK * HH + i] + hb1[n];
    g_hid[i] = fmaxf(s, 0.f);
}

// ---------------- fused FFN (synchronous, h-tile resident) ----------------
#define FFN_SMEM_BYTES ((8448 + 4608 + 8448) * 4)
__global__ __launch_bounds__(256) void k_ffn(const float* __restrict__ B1,
                                             const float* __restrict__ B2) {
    int g = blockIdx.x;
    if (g >= g_ngroups) return;
    int half = blockIdx.y;
    int e = g_grp_expert[g];
    int tid = threadIdx.x, lane = tid & 31, w = tid >> 5;

    extern __shared__ float sm[];
    float* sA = sm;                  // 64 x 132 (h tile, resident)
    float* sW = sm + 8448;           // 128 x 36 (weight chunk)
    float* sF = sm + 8448 + 4608;    // 64 x 132 (f1 chunk)

    const float* hb  = g_h + ((size_t)g * 128 + half * 64) * 128;
    const float* w1b = g_w1t + (size_t)e * 1024 * 128;
    const float* w2b = g_w2t + (size_t)e * 128 * 1024;

#pragma unroll
    for (int it = 0; it < 8; it++) {
        int i = tid + it * 256;
        int r = i >> 5, q = (i & 31) * 4;
        *reinterpret_cast<float4*>(sA + r * 132 + q) =
            *reinterpret_cast<const float4*>(hb + (size_t)r * 128 + q);
    }

    int mt = w & 3;
    int nt_base = (w >> 2) * 8;
    int r0 = mt * 16 + (lane >> 2);

    float acc2[8][4];
#pragma unroll
    for (int j = 0; j < 8; j++)
#pragma unroll
        for (int k = 0; k < 4; k++) acc2[j][k] = 0.f;

    for (int c = 0; c < 8; c++) {
        float acc1[8][4];
#pragma unroll
        for (int j = 0; j < 8; j++)
#pragma unroll
            for (int k = 0; k < 4; k++) acc1[j][k] = 0.f;

        for (int kc = 0; kc < 4; kc++) {
#pragma unroll
            for (int it = 0; it < 4; it++) {
                int i = tid + it * 256;
                int r = i >> 3, q = (i & 7) * 4;
                *reinterpret_cast<float4*>(sW + r * 36 + q) =
                    *reinterpret_cast<const float4*>(w1b + (size_t)(c * 128 + r) * 128 + kc * 32 + q);
            }
            __syncthreads();
#pragma unroll
            for (int ks = 0; ks < 4; ks++) {
                int colA = kc * 32 + ks * 8 + (lane & 3);
                uint32_t a[4];
                a[0] = __float_as_uint(sA[r0 * 132 + colA]);
                a[1] = __float_as_uint(sA[(r0 + 8) * 132 + colA]);
                a[2] = __float_as_uint(sA[r0 * 132 + colA + 4]);
                a[3] = __float_as_uint(sA[(r0 + 8) * 132 + colA + 4]);
                int cw = ks * 8 + (lane & 3);
#pragma unroll
                for (int nt = 0; nt < 8; nt++) {
                    int nr = (nt_base + nt) * 8 + (lane >> 2);
                    uint32_t b[2];
                    b[0] = __float_as_uint(sW[nr * 36 + cw]);
                    b[1] = __float_as_uint(sW[nr * 36 + cw + 4]);
                    mma_tf32(acc1[nt], a, b);
                }
            }
            __syncthreads();
        }

#pragma unroll
        for (int nt = 0; nt < 8; nt++) {
            int nc = (nt_base + nt) * 8 + 2 * (lane & 3);
            float2 bv = *reinterpret_cast<const float2*>(B1 + (size_t)e * 1024 + c * 128 + nc);
            sF[r0 * 132 + nc]           = to_tf32(fmaxf(acc1[nt][0] + bv.x, 0.f));
            sF[r0 * 132 + nc + 1]       = to_tf32(fmaxf(acc1[nt][1] + bv.y, 0.f));
            sF[(r0 + 8) * 132 + nc]     = to_tf32(fmaxf(acc1[nt][2] + bv.x, 0.f));
            sF[(r0 + 8) * 132 + nc + 1] = to_tf32(fmaxf(acc1[nt][3] + bv.y, 0.f));
        }
        __syncthreads();

        for (int kc = 0; kc < 4; kc++) {
#pragma unroll
            for (int it = 0; it < 4; it++) {
                int i = tid + it * 256;
                int r = i >> 3, q = (i & 7) * 4;
                *reinterpret_cast<float4*>(sW + r * 36 + q) =
                    *reinterpret_cast<const float4*>(w2b + (size_t)r * 1024 + c * 128 + kc * 32 + q);
            }
            __syncthreads();
#pragma unroll
            for (int ks = 0; ks < 4; ks++) {
                int colA = kc * 32 + ks * 8 + (lane & 3);
                uint32_t a[4];
                a[0] = __float_as_uint(sF[r0 * 132 + colA]);
                a[1] = __float_as_uint(sF[(r0 + 8) * 132 + colA]);
                a[2] = __float_as_uint(sF[r0 * 132 + colA + 4]);
                a[3] = __float_as_uint(sF[(r0 + 8) * 132 + colA + 4]);
                int cw = ks * 8 + (lane & 3);
#pragma unroll
                for (int nt = 0; nt < 8; nt++) {
                    int nr = (nt_base + nt) * 8 + (lane >> 2);
                    uint32_t b[2];
                    b[0] = __float_as_uint(sW[nr * 36 + cw]);
                    b[1] = __float_as_uint(sW[nr * 36 + cw + 4]);
                    mma_tf32(acc2[nt], a, b);
                }
            }
            __syncthreads();
        }
    }
    {
        float* f2b = g_f2 + ((size_t)g * 128 + half * 64) * 128;
#pragma unroll
        for (int nt = 0; nt < 8; nt++) {
            int nc = (nt_base + nt) * 8 + 2 * (lane & 3);
            float2 bv = *reinterpret_cast<const float2*>(B2 + (size_t)e * 128 + nc);
            float2 o0, o1;
            o0.x = acc2[nt][0] + bv.x; o0.y = acc2[nt][1] + bv.y;
            o1.x = acc2[nt][2] + bv.x; o1.y = acc2[nt][3] + bv.y;
            *reinterpret_cast<float2*>(f2b + (size_t)r0 * 128 + nc) = o0;
            *reinterpret_cast<float2*>(f2b + (size_t)(r0 + 8) * 128 + nc) = o1;
        }
    }
}

// ---------------- attention ----------------
__global__ __launch_bounds__(128) void k_attn() {
    int sp = blockIdx.x;
    if (sp >= g_npad) return;
    if (g_sp_pair[sp] < 0) return;
    __shared__ float s_kv[32 * 261];
    int tid = threadIdx.x, lane = tid & 31, h = tid >> 5;
    for (int i = tid; i < 32 * 256; i += 128) {
        int r = i >> 8, c = i & 255;
        s_kv[r * 261 + c] = g_qkv[((size_t)sp * 32 + r) * 384 + 128 + c];
    }
    __syncthreads();
    float kreg[32];
#pragma unroll
    for (int d = 0; d < 32; d++) kreg[d] = s_kv[lane * 261 + h * 32 + d];
    const float* qb = g_qkv + (size_t)sp * 32 * 384;
    for (int q = 0; q < 32; q++) {
        const float4* qp = reinterpret_cast<const float4*>(qb + q * 384 + h * 32);
        float sc = 0.f;
#pragma unroll
        for (int d4 = 0; d4 < 8; d4++) {
            float4 q4 = qp[d4];
            sc += q4.x * kreg[d4 * 4] + q4.y * kreg[d4 * 4 + 1]
                + q4.z * kreg[d4 * 4 + 2] + q4.w * kreg[d4 * 4 + 3];
        }
        sc *= 0.1767766952966369f;
        float m = sc;
#pragma unroll
        for (int off = 16; off > 0; off >>= 1)
            m = fmaxf(m, __shfl_xor_sync(0xffffffffu, m, off));
        float pr = expf(sc - m);
        float ss = pr;
#pragma unroll
        for (int off = 16; off > 0; off >>= 1)
            ss += __shfl_xor_sync(0xffffffffu, ss, off);
        float att = pr / ss;
        float o = 0.f;
#pragma unroll
        for (int kk = 0; kk < 32; kk++) {
            float av = __shfl_sync(0xffffffffu, att, kk);
            o = fmaf(av, s_kv[kk * 261 + 128 + h * 32 + lane], o);
        }
        g_ao[((size_t)sp * 32 + q) * 128 + h * 32 + lane] = to_tf32(o);
    }
}

// ---------------- LN1 (residual uses UNROUNDED x, matching reference) ----------------
__global__ __launch_bounds__(128) void k_ln1(const float* __restrict__ ln1_g,
                                             const float* __restrict__ ln1_b) {
    int sp = blockIdx.x;
    if (sp >= g_npad) return;
    int pr = g_sp_pair[sp];
    if (pr < 0) return;
    int token = pr >> 1;
    int e = g_topidx[pr];
    int tid = threadIdx.x, lane = tid & 31, w = tid >> 5;
    const float* g1 = ln1_g + e * 128;
    const float* b1 = ln1_b + e * 128;
    for (int rr = 0; rr < 8; rr++) {
        int r = w * 8 + rr;
        float v[4]; float sum = 0.f, sq = 0.f;
#pragma unroll
        for (int j = 0; j < 4; j++) {
            int c = lane + 32 * j;
            v[j] = g_x[(size_t)token * ND + r * 128 + c]
                 + g_o[((size_t)sp * 32 + r) * 128 + c];
            sum += v[j]; sq += v[j] * v[j];
        }
#pragma unroll
        for (int off = 16; off > 0; off >>= 1) {
            sum += __shfl_xor_sync(0xffffffffu, sum, off);
            sq  += __shfl_xor_sync(0xffffffffu, sq, off);
        }
        float mu = sum * (1.f / 128.f);
        float var = sq * (1.f / 128.f) - mu * mu;
        float rs = rsqrtf(var + 1e-5f);
#pragma unroll
        for (int j = 0; j < 4; j++) {
            int c = lane + 32 * j;
            g_h[((size_t)sp * 32 + r) * 128 + c] = to_tf32((v[j] - mu) * rs * g1[c] + b1[c]);
        }
    }
}

// ---------------- finish ----------------
__global__ __launch_bounds__(128) void k_finish(const float* __restrict__ ln2_g,
                                                const float* __restrict__ ln2_b) {
    int t = blockIdx.x;
    int tid = threadIdx.x, lane = tid & 31, w = tid >> 5;
    float y[8][4];
#pragma unroll
    for (int rr = 0; rr < 8; rr++)
#pragma unroll
        for (int j = 0; j < 4; j++) y[rr][j] = 0.f;

    for (int slot = 0; slot < 2; slot++) {
        int pr = t * 2 + slot;
        int sp = g_tok_sp[pr];
        int e = g_topidx[pr];
        float gate = g_topgate[pr];
        const float* g2 = ln2_g + e * 128;
        const float* b2 = ln2_b + e * 128;
        for (int rr = 0; rr < 8; rr++) {
            int r = w * 8 + rr;
            float v[4]; float sum = 0.f, sq = 0.f;
#pragma unroll
            for (int j = 0; j < 4; j++) {
                int c = lane + 32 * j;
                v[j] = g_h[((size_t)sp * 32 + r) * 128 + c]
                     + g_f2[((size_t)sp * 32 + r) * 128 + c];
                sum += v[j]; sq += v[j] * v[j];
            }
#pragma unroll
            for (int off = 16; off > 0; off >>= 1) {
                sum += __shfl_xor_sync(0xffffffffu, sum, off);
                sq  += __shfl_xor_sync(0xffffffffu, sq, off);
            }
            float mu = sum * (1.f / 128.f);
            float var = sq * (1.f / 128.f) - mu * mu;
            float rs = rsqrtf(var + 1e-5f);
#pragma unroll
            for (int j = 0; j < 4; j++) {
                int c = lane + 32 * j;
                y[rr][j] += gate * ((v[j] - mu) * rs * g2[c] + b2[c]);
            }
        }
    }
    for (int rr = 0; rr < 8; rr++) {
        int r = w * 8 + rr;
#pragma unroll
        for (int j = 0; j < 4; j++) {
            int c = lane + 32 * j;
            g_y[(size_t)t * ND + r * 128 + c] = to_tf32(y[rr][j]);
        }
    }
}

// ---------------- head GEMV2 ----------------
__global__ void k_head2(const float* __restrict__ hw2, const float* __restrict__ hb2,
                        float* __restrict__ out_r) {
    int b = blockIdx.x;
    int j = threadIdx.x >> 5;
    int lane = threadIdx.x & 31;
    const float* hb = g_hid + (size_t)b * HH;
    const float* w = hw2 + (size_t)j * HH;
    float s = 0.f;
    for (int k = lane; k < HH; k += 32) s = fmaf(hb[k], w[k], s);
#pragma unroll
    for (int off = 16; off > 0; off >>= 1) s += __shfl_xor_sync(0xffffffffu, s, off);
    if (lane == 0) out_r[b * NR + j] = s + hb2[j];
}

// ---------------- loss ----------------
__global__ void k_loss(const float* __restrict__ gates, float* __restrict__ out_loss) {
    __shared__ float s_imp[8][32], s_ld[8][32], s_lse[256];
    int t = threadIdx.x;
    int e = t & 7, c = t >> 3;
    float imp = 0.f, ld = 0.f;
    for (int b = c; b < B_TOK; b += 32) {
        float g = gates[b * 8 + e];
        imp += g;
        if (g > 0.f) ld += 1.f;
    }
    s_imp[e][c] = imp; s_ld[e][c] = ld;
    float ls = 0.f;
    for (int b = t; b < B_TOK; b += 256) ls += g_lse[b];
    s_lse[t] = ls;
    __syncthreads();
    for (int s = 128; s > 0; s >>= 1) {
        if (t < s) s_lse[t] += s_lse[t + s];
        __syncthreads();
    }
    if (t == 0) {
        float I[8], L[8];
        float mi = 0.f, ml = 0.f;
        for (int e2 = 0; e2 < 8; e2++) {
            float si = 0.f, sl = 0.f;
            for (int c2 = 0; c2 < 32; c2++) { si += s_imp[e2][c2]; sl += s_ld[e2][c2]; }
            I[e2] = si; L[e2] = sl; mi += si; ml += sl;
        }
        mi *= 0.125f; ml *= 0.125f;
        float vi = 0.f, vl = 0.f;
        for (int e2 = 0; e2 < 8; e2++) {
            vi += (I[e2] - mi) * (I[e2] - mi);
            vl += (L[e2] - ml) * (L[e2] - ml);
        }
        vi /= 7.f; vl /= 7.f;
        float loss = vi / (mi * mi + 1e-10f) + vl / (ml * ml + 1e-10f)
                   + s_lse[0] * (1.f / (float)B_TOK);
        *out_loss = loss;
    }
}

// ---------------- launch ----------------
extern "C" void kernel_launch(void* const* d_in, const int* in_sizes, int n_in,
                              void* d_out, int out_size) {
    const float* z      = (const float*)d_in[0];
    const float* a      = (const float*)d_in[1];
    const float* w_gate = (const float*)d_in[2];
    const float* w_in   = (const float*)d_in[3];
    const float* b_in   = (const float*)d_in[4];
    const float* w_out  = (const float*)d_in[5];
    const float* b_out  = (const float*)d_in[6];
    const float* ln1_g  = (const float*)d_in[7];
    const float* ln1_b  = (const float*)d_in[8];
    const float* w1     = (const float*)d_in[9];
    const float* b1     = (const float*)d_in[10];
    const float* w2     = (const float*)d_in[11];
    const float* b2     = (const float*)d_in[12];
    const float* ln2_g  = (const float*)d_in[13];
    const float* ln2_b  = (const float*)d_in[14];
    const float* hw1    = (const float*)d_in[15];
    const float* hb1    = (const float*)d_in[16];
    const float* hw2    = (const float*)d_in[17];
    const float* hb2    = (const float*)d_in[18];

    float* out       = (float*)d_out;
    float* gates_out = out + B_TOK * NR;
    float* loss_out  = out + B_TOK * NR + B_TOK * NEXP;

    cudaFuncSetAttribute(k_gemm<0, 0>, cudaFuncAttributeMaxDynamicSharedMemorySize, GEMM_SMEM_BYTES);
    cudaFuncSetAttribute(k_gemm<1, 1>, cudaFuncAttributeMaxDynamicSharedMemorySize, GEMM_SMEM_BYTES);
    cudaFuncSetAttribute(k_head1, cudaFuncAttributeMaxDynamicSharedMemorySize, GEMM_SMEM_BYTES);
    cudaFuncSetAttribute(k_ffn, cudaFuncAttributeMaxDynamicSharedMemorySize, FFN_SMEM_BYTES);

    k_round<<<(RW4 + 255) / 256, 256>>>(w_in, w_out, w1, w2, hw1);
    k_concat<<<(B_TOK * ND) / 256, 256>>>(z, a);
    k_router<<<B_TOK, 256>>>(w_gate, gates_out);
    k_sort<<<1, 32>>>();

    k_gemm<0, 0><<<dim3(GROUP_MAX, 3), 256, GEMM_SMEM_BYTES>>>(b_in, 384);
    k_attn<<<PAIR_MAX, 128>>>();
    k_gemm<1, 1><<<dim3(GROUP_MAX, 1), 256, GEMM_SMEM_BYTES>>>(b_out, 128);
    k_ln1<<<PAIR_MAX, 128>>>(ln1_g, ln1_b);
    k_ffn<<<dim3(GROUP_MAX, 2), 256, FFN_SMEM_BYTES>>>(b1, b2);
    k_finish<<<B_TOK, 128>>>(ln2_g, ln2_b);
    k_head1<<<dim3(8, 4, 4), 256, GEMM_SMEM_BYTES>>>();
    k_head1red<<<(B_TOK * HH) / 256, 256>>>(hb1);
    k_head2<<<B_TOK, 128>>>(hw2, hb2, out);
    k_loss<<<1, 256>>>(gates_out, loss_out);
}

// round 9
// speedup vs baseline: 3.9905x; 1.2228x over previous
#include <cuda_runtime.h>
#include <cuda_bf16.h>
#include <cstdint>

// ---------------- problem constants ----------------
#define B_TOK   1024
#define NA      32
#define DZ      96
#define DA      32
#define DMODEL  128
#define ND      4096      // NA*DMODEL
#define NEXP    8
#define FF      1024
#define HH      512
#define NR      4
#define KTOP    2

#define PAIR_MAX  2072
#define GROUP_MAX 518

// ---------------- scratch ----------------
__device__ float g_x [B_TOK * ND];               // concat(z,a), UNROUNDED (router + LN1 residual)
__device__ float g_xt[B_TOK * ND];               // tf32-rounded copy (GEMM A operand)
__device__ float g_y [B_TOK * ND];
__device__ float g_qkv[(size_t)PAIR_MAX * 32 * 384];
__device__ float g_ao [(size_t)PAIR_MAX * 32 * 128];
__device__ float g_o  [(size_t)PAIR_MAX * 32 * 128];
__device__ float g_h  [(size_t)PAIR_MAX * 32 * 128];
__device__ float g_f2 [(size_t)PAIR_MAX * 32 * 128];
__device__ float g_hid[B_TOK * HH];
__device__ float g_hp [4 * B_TOK * HH];
__device__ float g_lse[B_TOK];
__device__ int   g_topidx[B_TOK * KTOP];
__device__ float g_topgate[B_TOK * KTOP];

// tf32-rounded weight copies (ONLY referenced from device code!)
__device__ float g_wint [NEXP * 384 * 128];
__device__ float g_woutt[NEXP * 128 * 128];
__device__ float g_w1t  [NEXP * 1024 * 128];
__device__ float g_w2t  [NEXP * 128 * 1024];
__device__ float g_hw1t [HH * ND];

__device__ int   g_ngroups;
__device__ int   g_npad;
__device__ int   g_grp_expert[GROUP_MAX];
__device__ int   g_sp_pair[PAIR_MAX];
__device__ int   g_tok_sp[B_TOK * KTOP];

// ---------------- helpers ----------------
__device__ __forceinline__ float to_tf32(float f) {
    uint32_t u;
    asm("cvt.rna.tf32.f32 %0, %1;" : "=r"(u) : "f"(f));
    return __uint_as_float(u);
}

__device__ __forceinline__ void mma_tf32(float* c, const uint32_t* a, const uint32_t* b) {
    asm volatile(
        "mma.sync.aligned.m16n8k8.row.col.f32.tf32.tf32.f32 "
        "{%0,%1,%2,%3},{%4,%5,%6,%7},{%8,%9},{%0,%1,%2,%3};"
        : "+f"(c[0]), "+f"(c[1]), "+f"(c[2]), "+f"(c[3])
        : "r"(a[0]), "r"(a[1]), "r"(a[2]), "r"(a[3]), "r"(b[0]), "r"(b[1]));
}

__device__ __forceinline__ void cp_async16(uint32_t saddr, const void* gaddr) {
    asm volatile("cp.async.cg.shared.global [%0], [%1], 16;\n" :: "r"(saddr), "l"(gaddr));
}
#define CP_COMMIT() asm volatile("cp.async.commit_group;\n")
#define CP_WAIT1()  asm volatile("cp.async.wait_group 1;\n")
#define CP_WAIT0()  asm volatile("cp.async.wait_group 0;\n")

// ---------------- weight rounding prep ----------------
#define RW0 (NEXP * 384 * 128)
#define RW1 (RW0 + NEXP * 128 * 128)
#define RW2 (RW1 + NEXP * 1024 * 128)
#define RW3 (RW2 + NEXP * 128 * 1024)
#define RW4 (RW3 + HH * ND)
__global__ void k_round(const float* __restrict__ w_in, const float* __restrict__ w_out,
                        const float* __restrict__ w1, const float* __restrict__ w2,
                        const float* __restrict__ hw1) {
    int i = blockIdx.x * 256 + threadIdx.x;
    if (i < RW0)      g_wint[i]        = to_tf32(w_in[i]);
    else if (i < RW1) g_woutt[i - RW0] = to_tf32(w_out[i - RW0]);
    else if (i < RW2) g_w1t[i - RW1]   = to_tf32(w1[i - RW1]);
    else if (i < RW3) g_w2t[i - RW2]   = to_tf32(w2[i - RW2]);
    else if (i < RW4) g_hw1t[i - RW3]  = to_tf32(hw1[i - RW3]);
}

// ---------------- concat: unrounded + rounded copies ----------------
__global__ void k_concat(const float* __restrict__ z, const float* __restrict__ a) {
    int idx = blockIdx.x * 256 + threadIdx.x;
    int dd = idx & 127;
    int row = idx >> 7;
    float v = (dd < DZ) ? z[row * DZ + dd] : a[row * DA + (dd - DZ)];
    g_x[idx]  = v;
    g_xt[idx] = to_tf32(v);
}

// ---------------- router (reads UNROUNDED x: exact top-k selection) ----------------
__global__ __launch_bounds__(256) void k_router(const float* __restrict__ w_gate,
                                                float* __restrict__ gates_out) {
    __shared__ float red[256 * 8];
    int b = blockIdx.x, tid = threadIdx.x;
    float p[8];
#pragma unroll
    for (int e = 0; e < 8; e++) p[e] = 0.f;
    const float* xb = g_x + (size_t)b * ND;
    for (int k = tid; k < ND; k += 256) {
        float xv = xb[k];
        const float4* wg = reinterpret_cast<const float4*>(w_gate + (size_t)k * 8);
        float4 w0 = wg[0], w1 = wg[1];
        p[0] = fmaf(xv, w0.x, p[0]); p[1] = fmaf(xv, w0.y, p[1]);
        p[2] = fmaf(xv, w0.z, p[2]); p[3] = fmaf(xv, w0.w, p[3]);
        p[4] = fmaf(xv, w1.x, p[4]); p[5] = fmaf(xv, w1.y, p[5]);
        p[6] = fmaf(xv, w1.z, p[6]); p[7] = fmaf(xv, w1.w, p[7]);
    }
#pragma unroll
    for (int e = 0; e < 8; e++) red[tid * 8 + e] = p[e];
    __syncthreads();
    for (int s = 128; s > 0; s >>= 1) {
        if (tid < s) {
#pragma unroll
            for (int e = 0; e < 8; e++) red[tid * 8 + e] += red[(tid + s) * 8 + e];
        }
        __syncthreads();
    }
    if (tid == 0) {
        float l[8];
#pragma unroll
        for (int e = 0; e < 8; e++) l[e] = red[e];
        int i0 = 0; float v0 = l[0];
#pragma unroll
        for (int e = 1; e < 8; e++) if (l[e] > v0) { v0 = l[e]; i0 = e; }
        int i1 = -1; float v1 = -3.4e38f;
#pragma unroll
        for (int e = 0; e < 8; e++) if (e != i0 && l[e] > v1) { v1 = l[e]; i1 = e; }
        float e1 = expf(v1 - v0);
        float inv = 1.f / (1.f + e1);
        float g0 = inv, g1v = e1 * inv;
#pragma unroll
        for (int e = 0; e < 8; e++)
            gates_out[b * 8 + e] = (e == i0) ? g0 : ((e == i1) ? g1v : 0.f);
        g_topidx[b * 2] = i0;  g_topidx[b * 2 + 1] = i1;
        g_topgate[b * 2] = g0; g_topgate[b * 2 + 1] = g1v;
        float s = 0.f;
#pragma unroll
        for (int e = 0; e < 8; e++) s += expf(l[e] - v0);
        g_lse[b] = v0 + logf(s);
    }
}

// ---------------- parallel deterministic counting sort ----------------
// 256 threads, 8 pairs each. Stable by pair index (identical output to serial).
__global__ __launch_bounds__(256) void k_sort() {
    __shared__ int s_cnt[256][8];
    __shared__ int s_ecnt[8];
    __shared__ int s_base[8];
    int t = threadIdx.x;
    int my[8];
    int lc[8] = {0, 0, 0, 0, 0, 0, 0, 0};
#pragma unroll
    for (int i = 0; i < 8; i++) {
        int e = g_topidx[t * 8 + i];
        my[i] = e;
        lc[e]++;
    }
#pragma unroll
    for (int e = 0; e < 8; e++) s_cnt[t][e] = lc[e];
    __syncthreads();
    // exclusive scan across threads, one scanner lane per expert
    if (t < 8) {
        int off = 0;
        for (int i = 0; i < 256; i++) {
            int v = s_cnt[i][t];
            s_cnt[i][t] = off;
            off += v;
        }
        s_ecnt[t] = off;
    }
    __syncthreads();
    if (t == 0) {
        int o = 0, g = 0;
        for (int e = 0; e < 8; e++) {
            s_base[e] = o;
            int pc = (s_ecnt[e] + 3) & ~3;
            for (int i = 0; i < (pc >> 2); i++) g_grp_expert[g++] = e;
            o += pc;
        }
        g_ngroups = g;
        g_npad = o;
    }
    __syncthreads();
    // stable placement (s_cnt[t][e] currently = this thread's exclusive offset)
#pragma unroll
    for (int i = 0; i < 8; i++) {
        int p = t * 8 + i;
        int e = my[i];
        int sp = s_base[e] + s_cnt[t][e]++;
        g_sp_pair[sp] = p;
        g_tok_sp[p] = sp;
    }
    if (t < 8) {
        int start = s_base[t] + s_ecnt[t];
        int end = s_base[t] + ((s_ecnt[t] + 3) & ~3);
        for (int sp = start; sp < end; sp++) g_sp_pair[sp] = -1;
    }
}

// ---------------- cp.async stage helpers ----------------
__device__ __forceinline__ void gemm_issue(uint32_t smu, int buf, int kc,
                                           const float* const* s_ab,
                                           const float* wb, int tid) {
#pragma unroll
    for (int it = 0; it < 4; it++) {
        int i = tid + it * 256;
        int r = i >> 3, q = (i & 7) * 4;
        cp_async16(smu + (uint32_t)(buf * 4608 + r * 36 + q) * 4,
                   s_ab[r >> 5] + (size_t)(r & 31) * 128 + kc + q);
        cp_async16(smu + (uint32_t)(9216 + buf * 4608 + r * 36 + q) * 4,
                   wb + (size_t)r * 128 + kc + q);
    }
    CP_COMMIT();
}

__device__ __forceinline__ void head_issue(uint32_t smu, int buf, int kc,
                                           const float* Ab, const float* Bb, int tid) {
#pragma unroll
    for (int it = 0; it < 4; it++) {
        int i = tid + it * 256;
        int r = i >> 3, q = (i & 7) * 4;
        cp_async16(smu + (uint32_t)(buf * 4608 + r * 36 + q) * 4,
                   Ab + (size_t)r * ND + kc + q);
        cp_async16(smu + (uint32_t)(9216 + buf * 4608 + r * 36 + q) * 4,
                   Bb + (size_t)r * ND + kc + q);
    }
    CP_COMMIT();
}

// ---------------- tf32 batched GEMM (cp.async double-buffered) ----------------
#define GEMM_SMEM_BYTES 73728
template<int SRC, int DST>
__global__ __launch_bounds__(256) void k_gemm(const float* __restrict__ bias, int Ntot) {
    int g = blockIdx.x;
    if (g >= g_ngroups) return;
    int e = g_grp_expert[g];
    int n0 = blockIdx.y * 128;
    int tid = threadIdx.x, lane = tid & 31, w = tid >> 5;

    extern __shared__ float sm[];
    uint32_t smu = (uint32_t)__cvta_generic_to_shared(sm);
    __shared__ const float* s_ab[4];
    if (tid < 4) {
        const float* ab;
        if (SRC == 0) {
            int pr = g_sp_pair[g * 4 + tid];
            int tok = (pr >= 0) ? (pr >> 1) : 0;
            ab = g_xt + (size_t)tok * ND;
        } else {
            ab = g_ao + (size_t)(g * 4 + tid) * 32 * 128;
        }
        s_ab[tid] = ab;
    }
    __syncthreads();

    const float* W = (SRC == 0) ? g_wint : g_woutt;
    const float* wb = W + (size_t)e * Ntot * 128 + (size_t)n0 * 128;

    float acc[2][8][4];
#pragma unroll
    for (int i = 0; i < 2; i++)
#pragma unroll
        for (int j = 0; j < 8; j++)
#pragma unroll
            for (int k = 0; k < 4; k++) acc[i][j][k] = 0.f;

    int mt_base = (w & 3) * 2;
    int nt_base = (w >> 2) * 8;

    gemm_issue(smu, 0, 0, s_ab, wb, tid);
    for (int c = 0; c < 4; c++) {
        if (c + 1 < 4) { gemm_issue(smu, (c + 1) & 1, (c + 1) * 32, s_ab, wb, tid); CP_WAIT1(); }
        else CP_WAIT0();
        __syncthreads();
        const float* sA = sm + (c & 1) * 4608;
        const float* sB = sm + 9216 + (c & 1) * 4608;
#pragma unroll
        for (int ks = 0; ks < 4; ks++) {
            int col = ks * 8 + (lane & 3);
            uint32_t a[2][4];
#pragma unroll
            for (int mt = 0; mt < 2; mt++) {
                int r0 = (mt_base + mt) * 16 + (lane >> 2);
                a[mt][0] = __float_as_uint(sA[r0 * 36 + col]);
                a[mt][1] = __float_as_uint(sA[(r0 + 8) * 36 + col]);
                a[mt][2] = __float_as_uint(sA[r0 * 36 + col + 4]);
                a[mt][3] = __float_as_uint(sA[(r0 + 8) * 36 + col + 4]);
            }
#pragma unroll
            for (int nt = 0; nt < 8; nt++) {
                int nr = (nt_base + nt) * 8 + (lane >> 2);
                uint32_t b[2];
                b[0] = __float_as_uint(sB[nr * 36 + col]);
                b[1] = __float_as_uint(sB[nr * 36 + col + 4]);
                mma_tf32(acc[0][nt], a[0], b);
                mma_tf32(acc[1][nt], a[1], b);
            }
        }
        __syncthreads();
    }

    float* Cb = (DST == 0) ? g_qkv : g_o;
#pragma unroll
    for (int mt = 0; mt < 2; mt++) {
        int r0 = (mt_base + mt) * 16 + (lane >> 2);
        int r1 = r0 + 8;
#pragma unroll
        for (int nt = 0; nt < 8; nt++) {
            int nc = n0 + (nt_base + nt) * 8 + 2 * (lane & 3);
            float2 bv = *reinterpret_cast<const float2*>(bias + (size_t)e * Ntot + nc);
            float2 o0, o1;
            o0.x = acc[mt][nt][0] + bv.x; o0.y = acc[mt][nt][1] + bv.y;
            o1.x = acc[mt][nt][2] + bv.x; o1.y = acc[mt][nt][3] + bv.y;
            *reinterpret_cast<float2*>(Cb + ((size_t)g * 128 + r0) * Ntot + nc) = o0;
            *reinterpret_cast<float2*>(Cb + ((size_t)g * 128 + r1) * Ntot + nc) = o1;
        }
    }
}

// ---------------- head1: split-K tf32 GEMM (cp.async double-buffered) ----------------
__global__ __launch_bounds__(256) void k_head1() {
    int bm = blockIdx.x, bn = blockIdx.y, ks4 = blockIdx.z;
    int tid = threadIdx.x, lane = tid & 31, w = tid >> 5;

    extern __shared__ float sm[];
    uint32_t smu = (uint32_t)__cvta_generic_to_shared(sm);

    const float* Ab = g_y + (size_t)(bm * 128) * ND + ks4 * 1024;
    const float* Bb = g_hw1t + (size_t)(bn * 128) * ND + ks4 * 1024;

    float acc[2][8][4];
#pragma unroll
    for (int i = 0; i < 2; i++)
#pragma unroll
        for (int j = 0; j < 8; j++)
#pragma unroll
            for (int k = 0; k < 4; k++) acc[i][j][k] = 0.f;

    int mt_base = (w & 3) * 2;
    int nt_base = (w >> 2) * 8;

    head_issue(smu, 0, 0, Ab, Bb, tid);
    for (int c = 0; c < 32; c++) {
        if (c + 1 < 32) { head_issue(smu, (c + 1) & 1, (c + 1) * 32, Ab, Bb, tid); CP_WAIT1(); }
        else CP_WAIT0();
        __syncthreads();
        const float* sA = sm + (c & 1) * 4608;
        const float* sB = sm + 9216 + (c & 1) * 4608;
#pragma unroll
        for (int ks = 0; ks < 4; ks++) {
            int col = ks * 8 + (lane & 3);
            uint32_t a[2][4];
#pragma unroll
            for (int mt = 0; mt < 2; mt++) {
                int r0 = (mt_base + mt) * 16 + (lane >> 2);
                a[mt][0] = __float_as_uint(sA[r0 * 36 + col]);
                a[mt][1] = __float_as_uint(sA[(r0 + 8) * 36 + col]);
                a[mt][2] = __float_as_uint(sA[r0 * 36 + col + 4]);
                a[mt][3] = __float_as_uint(sA[(r0 + 8) * 36 + col + 4]);
            }
#pragma unroll
            for (int nt = 0; nt < 8; nt++) {
                int nr = (nt_base + nt) * 8 + (lane >> 2);
                uint32_t b[2];
                b[0] = __float_as_uint(sB[nr * 36 + col]);
                b[1] = __float_as_uint(sB[nr * 36 + col + 4]);
                mma_tf32(acc[0][nt], a[0], b);
                mma_tf32(acc[1][nt], a[1], b);
            }
        }
        __syncthreads();
    }

    float* dst = g_hp + ((size_t)ks4 * B_TOK + bm * 128) * HH + bn * 128;
#pragma unroll
    for (int mt = 0; mt < 2; mt++) {
        int r0 = (mt_base + mt) * 16 + (lane >> 2);
        int r1 = r0 + 8;
#pragma unroll
        for (int nt = 0; nt < 8; nt++) {
            int nc = (nt_base + nt) * 8 + 2 * (lane & 3);
            float2 o0, o1;
            o0.x = acc[mt][nt][0]; o0.y = acc[mt][nt][1];
            o1.x = acc[mt][nt][2]; o1.y = acc[mt][nt][3];
            *reinterpret_cast<float2*>(dst + (size_t)r0 * HH + nc) = o0;
            *reinterpret_cast<float2*>(dst + (size_t)r1 * HH + nc) = o1;
        }
    }
}

__global__ void k_head1red(const float* __restrict__ hb1) {
    int i = blockIdx.x * 256 + threadIdx.x;
    int n = i & (HH - 1);
    float s = g_hp[i] + g_hp[B_TOK * HH + i] + g_hp[2 * B_TOK * HH + i]
            + g_hp[3 * B_TOK * HH + i] + hb1[n];
    g_hid[i] = fmaxf(s, 0.f);
}

// ---------------- fused FFN (cp.async 2-deep pipelined weight stream) ----------------
// smem floats: sA[64*132]=8448 | sW[2][128*36]=9216 | sF[64*132]=8448 => 104448 B
#define FFN_SMEM_BYTES ((8448 + 9216 + 8448) * 4)
__device__ __forceinline__ void ffn_issue(uint32_t smu, int s,
                                          const float* w1b, const float* w2b, int tid) {
    int c = s >> 3, ph = (s >> 2) & 1, kc = s & 3;
    const float* base;
    int rstride;
    if (ph) { base = w2b + c * 128 + kc * 32;                 rstride = 1024; }
    else    { base = w1b + (size_t)(c * 128) * 128 + kc * 32; rstride = 128; }
#pragma unroll
    for (int it = 0; it < 4; it++) {
        int i = tid + it * 256;
        int r = i >> 3, q = (i & 7) * 4;
        cp_async16(smu + (uint32_t)(8448 + (s & 1) * 4608 + r * 36 + q) * 4,
                   base + (size_t)r * rstride + q);
    }
    CP_COMMIT();
}

__global__ __launch_bounds__(256) void k_ffn(const float* __restrict__ B1,
                                             const float* __restrict__ B2) {
    int g = blockIdx.x;
    if (g >= g_ngroups) return;
    int half = blockIdx.y;
    int e = g_grp_expert[g];
    int tid = threadIdx.x, lane = tid & 31, w = tid >> 5;

    extern __shared__ float sm[];
    float* sA = sm;                  // 64 x 132 (h tile, resident)
    float* sW = sm + 8448;           // 2 x 128 x 36 (weight ring)
    float* sF = sm + 8448 + 9216;    // 64 x 132 (f1 chunk)
    uint32_t smu = (uint32_t)__cvta_generic_to_shared(sm);

    const float* hb  = g_h + ((size_t)g * 128 + half * 64) * 128;
    const float* w1b = g_w1t + (size_t)e * 1024 * 128;
    const float* w2b = g_w2t + (size_t)e * 128 * 1024;

#pragma unroll
    for (int it = 0; it < 8; it++) {
        int i = tid + it * 256;
        int r = i >> 5, q = (i & 31) * 4;
        *reinterpret_cast<float4*>(sA + r * 132 + q) =
            *reinterpret_cast<const float4*>(hb + (size_t)r * 128 + q);
    }

    int mt = w & 3;
    int nt_base = (w >> 2) * 8;
    int r0 = mt * 16 + (lane >> 2);

    float acc1[8][4], acc2[8][4];
#pragma unroll
    for (int j = 0; j < 8; j++)
#pragma unroll
        for (int k = 0; k < 4; k++) acc2[j][k] = 0.f;

    ffn_issue(smu, 0, w1b, w2b, tid);
    ffn_issue(smu, 1, w1b, w2b, tid);

    for (int s = 0; s < 64; s++) {
        if (s < 63) CP_WAIT1(); else CP_WAIT0();
        __syncthreads();                       // sW[s&1] ready; also covers sA load at s=0
        if ((s & 7) == 0) {
#pragma unroll
            for (int j = 0; j < 8; j++)
#pragma unroll
                for (int k = 0; k < 4; k++) acc1[j][k] = 0.f;
        }
        int ph = (s >> 2) & 1;
        int kc = s & 3;
        const float* sWb = sW + (s & 1) * 4608;
        if (!ph) {
#pragma unroll
            for (int ks = 0; ks < 4; ks++) {
                int colA = kc * 32 + ks * 8 + (lane & 3);
                uint32_t a[4];
                a[0] = __float_as_uint(sA[r0 * 132 + colA]);
                a[1] = __float_as_uint(sA[(r0 + 8) * 132 + colA]);
                a[2] = __float_as_uint(sA[r0 * 132 + colA + 4]);
                a[3] = __float_as_uint(sA[(r0 + 8) * 132 + colA + 4]);
                int cw = ks * 8 + (lane & 3);
#pragma unroll
                for (int nt = 0; nt < 8; nt++) {
                    int nr = (nt_base + nt) * 8 + (lane >> 2);
                    uint32_t b[2];
                    b[0] = __float_as_uint(sWb[nr * 36 + cw]);
                    b[1] = __float_as_uint(sWb[nr * 36 + cw + 4]);
                    mma_tf32(acc1[nt], a, b);
                }
            }
        } else {
#pragma unroll
            for (int ks = 0; ks < 4; ks++) {
                int colA = kc * 32 + ks * 8 + (lane & 3);
                uint32_t a[4];
                a[0] = __float_as_uint(sF[r0 * 132 + colA]);
                a[1] = __float_as_uint(sF[(r0 + 8) * 132 + colA]);
                a[2] = __float_as_uint(sF[r0 * 132 + colA + 4]);
                a[3] = __float_as_uint(sF[(r0 + 8) * 132 + colA + 4]);
                int cw = ks * 8 + (lane & 3);
#pragma unroll
                for (int nt = 0; nt < 8; nt++) {
                    int nr = (nt_base + nt) * 8 + (lane >> 2);
                    uint32_t b[2];
                    b[0] = __float_as_uint(sWb[nr * 36 + cw]);
                    b[1] = __float_as_uint(sWb[nr * 36 + cw + 4]);
                    mma_tf32(acc2[nt], a, b);
                }
            }
        }
        __syncthreads();                       // mma done before sW[s&1] reuse / sF write
        if ((s & 7) == 3) {
            int c = s >> 3;
#pragma unroll
            for (int nt = 0; nt < 8; nt++) {
                int nc = (nt_base + nt) * 8 + 2 * (lane & 3);
                float2 bv = *reinterpret_cast<const float2*>(B1 + (size_t)e * 1024 + c * 128 + nc);
                sF[r0 * 132 + nc]           = to_tf32(fmaxf(acc1[nt][0] + bv.x, 0.f));
                sF[r0 * 132 + nc + 1]       = to_tf32(fmaxf(acc1[nt][1] + bv.y, 0.f));
                sF[(r0 + 8) * 132 + nc]     = to_tf32(fmaxf(acc1[nt][2] + bv.x, 0.f));
                sF[(r0 + 8) * 132 + nc + 1] = to_tf32(fmaxf(acc1[nt][3] + bv.y, 0.f));
            }
            __syncthreads();                   // sF visible before stage-2 reads
        }
        if (s + 2 < 64) ffn_issue(smu, s + 2, w1b, w2b, tid);
    }

    {
        float* f2b = g_f2 + ((size_t)g * 128 + half * 64) * 128;
#pragma unroll
        for (int nt = 0; nt < 8; nt++) {
            int nc = (nt_base + nt) * 8 + 2 * (lane & 3);
            float2 bv = *reinterpret_cast<const float2*>(B2 + (size_t)e * 128 + nc);
            float2 o0, o1;
            o0.x = acc2[nt][0] + bv.x; o0.y = acc2[nt][1] + bv.y;
            o1.x = acc2[nt][2] + bv.x; o1.y = acc2[nt][3] + bv.y;
            *reinterpret_cast<float2*>(f2b + (size_t)r0 * 128 + nc) = o0;
            *reinterpret_cast<float2*>(f2b + (size_t)(r0 + 8) * 128 + nc) = o1;
        }
    }
}

// ---------------- attention ----------------
__global__ __launch_bounds__(128) void k_attn() {
    int sp = blockIdx.x;
    if (sp >= g_npad) return;
    if (g_sp_pair[sp] < 0) return;
    __shared__ float s_kv[32 * 261];
    int tid = threadIdx.x, lane = tid & 31, h = tid >> 5;
    for (int i = tid; i < 32 * 256; i += 128) {
        int r = i >> 8, c = i & 255;
        s_kv[r * 261 + c] = g_qkv[((size_t)sp * 32 + r) * 384 + 128 + c];
    }
    __syncthreads();
    float kreg[32];
#pragma unroll
    for (int d = 0; d < 32; d++) kreg[d] = s_kv[lane * 261 + h * 32 + d];
    const float* qb = g_qkv + (size_t)sp * 32 * 384;
    for (int q = 0; q < 32; q++) {
        const float4* qp = reinterpret_cast<const float4*>(qb + q * 384 + h * 32);
        float sc = 0.f;
#pragma unroll
        for (int d4 = 0; d4 < 8; d4++) {
            float4 q4 = qp[d4];
            sc += q4.x * kreg[d4 * 4] + q4.y * kreg[d4 * 4 + 1]
                + q4.z * kreg[d4 * 4 + 2] + q4.w * kreg[d4 * 4 + 3];
        }
        sc *= 0.1767766952966369f;
        float m = sc;
#pragma unroll
        for (int off = 16; off > 0; off >>= 1)
            m = fmaxf(m, __shfl_xor_sync(0xffffffffu, m, off));
        float pr = expf(sc - m);
        float ss = pr;
#pragma unroll
        for (int off = 16; off > 0; off >>= 1)
            ss += __shfl_xor_sync(0xffffffffu, ss, off);
        float att = pr / ss;
        float o = 0.f;
#pragma unroll
        for (int kk = 0; kk < 32; kk++) {
            float av = __shfl_sync(0xffffffffu, att, kk);
            o = fmaf(av, s_kv[kk * 261 + 128 + h * 32 + lane], o);
        }
        g_ao[((size_t)sp * 32 + q) * 128 + h * 32 + lane] = to_tf32(o);
    }
}

// ---------------- LN1 (residual uses UNROUNDED x) ----------------
__global__ __launch_bounds__(128) void k_ln1(const float* __restrict__ ln1_g,
                                             const float* __restrict__ ln1_b) {
    int sp = blockIdx.x;
    if (sp >= g_npad) return;
    int pr = g_sp_pair[sp];
    if (pr < 0) return;
    int token = pr >> 1;
    int e = g_topidx[pr];
    int tid = threadIdx.x, lane = tid & 31, w = tid >> 5;
    const float* g1 = ln1_g + e * 128;
    const float* b1 = ln1_b + e * 128;
    for (int rr = 0; rr < 8; rr++) {
        int r = w * 8 + rr;
        float v[4]; float sum = 0.f, sq = 0.f;
#pragma unroll
        for (int j = 0; j < 4; j++) {
            int c = lane + 32 * j;
            v[j] = g_x[(size_t)token * ND + r * 128 + c]
                 + g_o[((size_t)sp * 32 + r) * 128 + c];
            sum += v[j]; sq += v[j] * v[j];
        }
#pragma unroll
        for (int off = 16; off > 0; off >>= 1) {
            sum += __shfl_xor_sync(0xffffffffu, sum, off);
            sq  += __shfl_xor_sync(0xffffffffu, sq, off);
        }
        float mu = sum * (1.f / 128.f);
        float var = sq * (1.f / 128.f) - mu * mu;
        float rs = rsqrtf(var + 1e-5f);
#pragma unroll
        for (int j = 0; j < 4; j++) {
            int c = lane + 32 * j;
            g_h[((size_t)sp * 32 + r) * 128 + c] = to_tf32((v[j] - mu) * rs * g1[c] + b1[c]);
        }
    }
}

// ---------------- finish ----------------
__global__ __launch_bounds__(128) void k_finish(const float* __restrict__ ln2_g,
                                                const float* __restrict__ ln2_b) {
    int t = blockIdx.x;
    int tid = threadIdx.x, lane = tid & 31, w = tid >> 5;
    float y[8][4];
#pragma unroll
    for (int rr = 0; rr < 8; rr++)
#pragma unroll
        for (int j = 0; j < 4; j++) y[rr][j] = 0.f;

    for (int slot = 0; slot < 2; slot++) {
        int pr = t * 2 + slot;
        int sp = g_tok_sp[pr];
        int e = g_topidx[pr];
        float gate = g_topgate[pr];
        const float* g2 = ln2_g + e * 128;
        const float* b2 = ln2_b + e * 128;
        for (int rr = 0; rr < 8; rr++) {
            int r = w * 8 + rr;
            float v[4]; float sum = 0.f, sq = 0.f;
#pragma unroll
            for (int j = 0; j < 4; j++) {
                int c = lane + 32 * j;
                v[j] = g_h[((size_t)sp * 32 + r) * 128 + c]
                     + g_f2[((size_t)sp * 32 + r) * 128 + c];
                sum += v[j]; sq += v[j] * v[j];
            }
#pragma unroll
            for (int off = 16; off > 0; off >>= 1) {
                sum += __shfl_xor_sync(0xffffffffu, sum, off);
                sq  += __shfl_xor_sync(0xffffffffu, sq, off);
            }
            float mu = sum * (1.f / 128.f);
            float var = sq * (1.f / 128.f) - mu * mu;
            float rs = rsqrtf(var + 1e-5f);
#pragma unroll
            for (int j = 0; j < 4; j++) {
                int c = lane + 32 * j;
                y[rr][j] += gate * ((v[j] - mu) * rs * g2[c] + b2[c]);
            }
        }
    }
    for (int rr = 0; rr < 8; rr++) {
        int r = w * 8 + rr;
#pragma unroll
        for (int j = 0; j < 4; j++) {
            int c = lane + 32 * j;
            g_y[(size_t)t * ND + r * 128 + c] = to_tf32(y[rr][j]);
        }
    }
}

// ---------------- head GEMV2 ----------------
__global__ void k_head2(const float* __restrict__ hw2, const float* __restrict__ hb2,
                        float* __restrict__ out_r) {
    int b = blockIdx.x;
    int j = threadIdx.x >> 5;
    int lane = threadIdx.x & 31;
    const float* hb = g_hid + (size_t)b * HH;
    const float* w = hw2 + (size_t)j * HH;
    float s = 0.f;
    for (int k = lane; k < HH; k += 32) s = fmaf(hb[k], w[k], s);
#pragma unroll
    for (int off = 16; off > 0; off >>= 1) s += __shfl_xor_sync(0xffffffffu, s, off);
    if (lane == 0) out_r[b * NR + j] = s + hb2[j];
}

// ---------------- loss ----------------
__global__ void k_loss(const float* __restrict__ gates, float* __restrict__ out_loss) {
    __shared__ float s_imp[8][32], s_ld[8][32], s_lse[256];
    int t = threadIdx.x;
    int e = t & 7, c = t >> 3;
    float imp = 0.f, ld = 0.f;
    for (int b = c; b < B_TOK; b += 32) {
        float g = gates[b * 8 + e];
        imp += g;
        if (g > 0.f) ld += 1.f;
    }
    s_imp[e][c] = imp; s_ld[e][c] = ld;
    float ls = 0.f;
    for (int b = t; b < B_TOK; b += 256) ls += g_lse[b];
    s_lse[t] = ls;
    __syncthreads();
    for (int s = 128; s > 0; s >>= 1) {
        if (t < s) s_lse[t] += s_lse[t + s];
        __syncthreads();
    }
    if (t == 0) {
        float I[8], L[8];
        float mi = 0.f, ml = 0.f;
        for (int e2 = 0; e2 < 8; e2++) {
            float si = 0.f, sl = 0.f;
            for (int c2 = 0; c2 < 32; c2++) { si += s_imp[e2][c2]; sl += s_ld[e2][c2]; }
            I[e2] = si; L[e2] = sl; mi += si; ml += sl;
        }
        mi *= 0.125f; ml *= 0.125f;
        float vi = 0.f, vl = 0.f;
        for (int e2 = 0; e2 < 8; e2++) {
            vi += (I[e2] - mi) * (I[e2] - mi);
            vl += (L[e2] - ml) * (L[e2] - ml);
        }
        vi /= 7.f; vl /= 7.f;
        float loss = vi / (mi * mi + 1e-10f) + vl / (ml * ml + 1e-10f)
                   + s_lse[0] * (1.f / (float)B_TOK);
        *out_loss = loss;
    }
}

// ---------------- launch ----------------
extern "C" void kernel_launch(void* const* d_in, const int* in_sizes, int n_in,
                              void* d_out, int out_size) {
    const float* z      = (const float*)d_in[0];
    const float* a      = (const float*)d_in[1];
    const float* w_gate = (const float*)d_in[2];
    const float* w_in   = (const float*)d_in[3];
    const float* b_in   = (const float*)d_in[4];
    const float* w_out  = (const float*)d_in[5];
    const float* b_out  = (const float*)d_in[6];
    const float* ln1_g  = (const float*)d_in[7];
    const float* ln1_b  = (const float*)d_in[8];
    const float* w1     = (const float*)d_in[9];
    const float* b1     = (const float*)d_in[10];
    const float* w2     = (const float*)d_in[11];
    const float* b2     = (const float*)d_in[12];
    const float* ln2_g  = (const float*)d_in[13];
    const float* ln2_b  = (const float*)d_in[14];
    const float* hw1    = (const float*)d_in[15];
    const float* hb1    = (const float*)d_in[16];
    const float* hw2    = (const float*)d_in[17];
    const float* hb2    = (const float*)d_in[18];

    float* out       = (float*)d_out;
    float* gates_out = out + B_TOK * NR;
    float* loss_out  = out + B_TOK * NR + B_TOK * NEXP;

    cudaFuncSetAttribute(k_gemm<0, 0>, cudaFuncAttributeMaxDynamicSharedMemorySize, GEMM_SMEM_BYTES);
    cudaFuncSetAttribute(k_gemm<1, 1>, cudaFuncAttributeMaxDynamicSharedMemorySize, GEMM_SMEM_BYTES);
    cudaFuncSetAttribute(k_head1, cudaFuncAttributeMaxDynamicSharedMemorySize, GEMM_SMEM_BYTES);
    cudaFuncSetAttribute(k_ffn, cudaFuncAttributeMaxDynamicSharedMemorySize, FFN_SMEM_BYTES);

    k_round<<<(RW4 + 255) / 256, 256>>>(w_in, w_out, w1, w2, hw1);
    k_concat<<<(B_TOK * ND) / 256, 256>>>(z, a);
    k_router<<<B_TOK, 256>>>(w_gate, gates_out);
    k_sort<<<1, 256>>>();

    k_gemm<0, 0><<<dim3(GROUP_MAX, 3), 256, GEMM_SMEM_BYTES>>>(b_in, 384);
    k_attn<<<PAIR_MAX, 128>>>();
    k_gemm<1, 1><<<dim3(GROUP_MAX, 1), 256, GEMM_SMEM_BYTES>>>(b_out, 128);
    k_ln1<<<PAIR_MAX, 128>>>(ln1_g, ln1_b);
    k_ffn<<<dim3(GROUP_MAX, 2), 256, FFN_SMEM_BYTES>>>(b1, b2);
    k_finish<<<B_TOK, 128>>>(ln2_g, ln2_b);
    k_head1<<<dim3(8, 4, 4), 256, GEMM_SMEM_BYTES>>>();
    k_head1red<<<(B_TOK * HH) / 256, 256>>>(hb1);
    k_head2<<<B_TOK, 128>>>(hw2, hb2, out);
    k_loss<<<1, 256>>>(gates_out, loss_out);
}